// round 5
// baseline (speedup 1.0000x reference)
#include <cuda_runtime.h>

// ---------------------------------------------------------------------------
// Problem constants
// ---------------------------------------------------------------------------
#define NB 64
#define NT 512
#define NF 1024
#define NL 128
#define NTOT (NT * NF)          // 524288 = T*F
#define NSEG 8                  // t-segments per batch in K1

// Output layout (flat concat in reference return order)
#define OFF_MU    0
#define OFF_STD   (NB * NL)                 // 8192
#define OFF_ZS    (2 * NB * NL)             // 16384
#define OFF_LOC   (3 * NB * NL)             // 24576
#define OFF_SCALE (3 * NB * NL + NB * NTOT) // 33579008

// ---------------------------------------------------------------------------
// Device scratch (no allocation allowed)
// ---------------------------------------------------------------------------
__device__ float g_hpart[NB * NSEG * NF];   // partial masked sums
__device__ float g_cntpart[NB * NSEG];      // partial mask counts
__device__ float g_zs[NB * NL];             // zs for decoder

// ---------------------------------------------------------------------------
// Helpers
// ---------------------------------------------------------------------------
__device__ __forceinline__ float softplus_f(float v) {
    // jax.nn.softplus = max(x,0) + log1p(exp(-|x|))
    return fmaxf(v, 0.0f) + log1pf(expf(-fabsf(v)));
}

__device__ __forceinline__ unsigned long long ffma2(unsigned long long a,
                                                    unsigned long long b,
                                                    unsigned long long c) {
    unsigned long long d;
    asm("fma.rn.f32x2 %0, %1, %2, %3;" : "=l"(d) : "l"(a), "l"(b), "l"(c));
    return d;
}

__device__ __forceinline__ unsigned long long dup_f32(float v) {
    unsigned int u = __float_as_uint(v);
    return ((unsigned long long)u << 32) | (unsigned long long)u;
}

// Threefry-2x32, 20 rounds — exact JAX key schedule
__device__ __forceinline__ void tf2x32(unsigned int k0, unsigned int k1,
                                       unsigned int x0, unsigned int x1,
                                       unsigned int& o0, unsigned int& o1) {
    unsigned int ks2 = k0 ^ k1 ^ 0x1BD11BDAu;
    x0 += k0; x1 += k1;
#define TF_R(r) { x0 += x1; x1 = (x1 << (r)) | (x1 >> (32 - (r))); x1 ^= x0; }
    TF_R(13) TF_R(15) TF_R(26) TF_R(6)
    x0 += k1;  x1 += ks2 + 1u;
    TF_R(17) TF_R(29) TF_R(16) TF_R(24)
    x0 += ks2; x1 += k0 + 2u;
    TF_R(13) TF_R(15) TF_R(26) TF_R(6)
    x0 += k0;  x1 += k1 + 3u;
    TF_R(17) TF_R(29) TF_R(16) TF_R(24)
    x0 += k1;  x1 += ks2 + 4u;
    TF_R(13) TF_R(15) TF_R(26) TF_R(6)
    x0 += ks2; x1 += k0 + 5u;
#undef TF_R
    o0 = x0; o1 = x1;
}

// XLA f32 erf_inv (Giles polynomial) — matches lax.erf_inv bit behavior closely
__device__ __forceinline__ float erfinv_xla(float x) {
    float w = -log1pf(-x * x);
    float p;
    if (w < 5.0f) {
        w = w - 2.5f;
        p = 2.81022636e-08f;
        p = fmaf(p, w, 3.43273939e-07f);
        p = fmaf(p, w, -3.5233877e-06f);
        p = fmaf(p, w, -4.39150654e-06f);
        p = fmaf(p, w, 0.00021858087f);
        p = fmaf(p, w, -0.00125372503f);
        p = fmaf(p, w, -0.00417768164f);
        p = fmaf(p, w, 0.246640727f);
        p = fmaf(p, w, 1.50140941f);
    } else {
        w = sqrtf(w) - 3.0f;
        p = -0.000200214257f;
        p = fmaf(p, w, 0.000100950558f);
        p = fmaf(p, w, 0.00134934322f);
        p = fmaf(p, w, -0.00367342844f);
        p = fmaf(p, w, 0.00573950773f);
        p = fmaf(p, w, -0.0076224613f);
        p = fmaf(p, w, 0.00943887047f);
        p = fmaf(p, w, 1.00167406f);
        p = fmaf(p, w, 2.83297682f);
    }
    return p * x;
}

// ---------------------------------------------------------------------------
// K1: fused mask + masked sum-pool over t.  grid (NB, NSEG), 256 threads.
// ---------------------------------------------------------------------------
__global__ __launch_bounds__(256) void k1_pool(const float* __restrict__ x) {
    const int b = blockIdx.x;
    const int s = blockIdx.y;
    const int warp = threadIdx.x >> 5;
    const int lane = threadIdx.x & 31;

    __shared__ float hsh[NF];
    __shared__ int cnt_sh;
    for (int i = threadIdx.x; i < NF; i += 256) hsh[i] = 0.0f;
    if (threadIdx.x == 0) cnt_sh = 0;
    __syncthreads();

    float acc[32];
#pragma unroll
    for (int j = 0; j < 32; ++j) acc[j] = 0.0f;
    int cnt = 0;

    const float* xb = x + ((long long)b * NT + s * (NT / NSEG)) * NF;
    const int rows = NT / NSEG;  // 64
    for (int r = warp; r < rows; r += 8) {
        const float* row = xb + (long long)r * NF;
        float v[32];
        float sum = 0.0f;
#pragma unroll
        for (int j = 0; j < 32; ++j) {
            v[j] = row[lane + 32 * j];
            sum += v[j];
        }
#pragma unroll
        for (int o = 16; o > 0; o >>= 1) sum += __shfl_xor_sync(0xffffffffu, sum, o);
        if (sum != 0.0f) {
            cnt++;
#pragma unroll
            for (int j = 0; j < 32; ++j) acc[j] += v[j];
        }
    }

#pragma unroll
    for (int j = 0; j < 32; ++j) atomicAdd(&hsh[lane + 32 * j], acc[j]);
    if (lane == 0) atomicAdd(&cnt_sh, cnt);
    __syncthreads();

    const int part = b * NSEG + s;
    for (int i = threadIdx.x; i < NF; i += 256) g_hpart[part * NF + i] = hsh[i];
    if (threadIdx.x == 0) g_cntpart[part] = (float)cnt_sh;
}

// ---------------------------------------------------------------------------
// K2: encoder heads + threefry eps + zs.  grid NB, 128 threads (thread = l).
// ---------------------------------------------------------------------------
__global__ __launch_bounds__(128) void k2_encode(
    const float* __restrict__ Wmu, const float* __restrict__ bmu,
    const float* __restrict__ Wstd, const float* __restrict__ bstd,
    const float* __restrict__ actionbias, const int* __restrict__ label,
    float* __restrict__ out) {
    const int b = blockIdx.x;
    const int l = threadIdx.x;

    __shared__ float hsh[NF];
    __shared__ float inv_denom;

    for (int f = l; f < NF; f += NL) {
        float sum = 0.0f;
#pragma unroll
        for (int p = 0; p < NSEG; ++p) sum += g_hpart[(b * NSEG + p) * NF + f];
        hsh[f] = sum;
    }
    if (l == 0) {
        float c = 0.0f;
#pragma unroll
        for (int p = 0; p < NSEG; ++p) c += g_cntpart[b * NSEG + p];
        inv_denom = 1.0f / fmaxf(c, 1.0f);
    }
    __syncthreads();
    const float inv = inv_denom;
    for (int f = l; f < NF; f += NL) hsh[f] *= inv;
    __syncthreads();

    float mu = bmu[l];
    float sp = bstd[l];
#pragma unroll 8
    for (int f = 0; f < NF; ++f) {
        const float hv = hsh[f];
        mu = fmaf(hv, Wmu[f * NL + l], mu);
        sp = fmaf(hv, Wstd[f * NL + l], sp);
    }
    const float stdv = softplus_f(sp);

    // eps: jax.random.normal(fold_in(key(0),1), (64,128)) with PARTITIONABLE
    // threefry (modern JAX default):
    //   bits[i] = o0 ^ o1 of threefry2x32(key, hi=idx>>32, lo=idx)
    unsigned int nk0, nk1;
    tf2x32(0u, 0u, 0u, 1u, nk0, nk1);          // fold_in(key(0), 1)
    const int idx = b * NL + l;                  // flat index into 8192
    unsigned int o0, o1;
    tf2x32(nk0, nk1, 0u, (unsigned int)idx, o0, o1);
    const unsigned int bits = o0 ^ o1;
    const float f01 = __uint_as_float(0x3F800000u | (bits >> 9)) - 1.0f;
    float u = fmaf(f01, 2.0f, -0.99999994f);     // lo = nextafter(-1,0); hi-lo rounds to 2.0f
    u = fmaxf(u, -0.99999994f);
    const float eps = 1.41421356237309515f * erfinv_xla(u);

    const float zs = mu + stdv * eps + actionbias[label[b] * NL + l];

    out[OFF_MU + idx]  = mu;
    out[OFF_STD + idx] = stdv;
    out[OFF_ZS + idx]  = zs;
    g_zs[idx] = zs;
}

// ---------------------------------------------------------------------------
// K3: decoder GEMM  loc[b,n] = sum_l zs[b,l]*W_dec[l,n] + b_dec[n]
// 2048 blocks x 256 threads. Thread = 2 columns (n, n+128) x 32 batch rows.
// zs transposed in shared as packed (b, b+1) float2 so one broadcast LDS.64
// feeds two fma.rn.f32x2 — FMA-pipe-bound at 128 FMA/cyc/SM.
// ---------------------------------------------------------------------------
__global__ __launch_bounds__(256) void k3_decoder(const float* __restrict__ Wd,
                                                  const float* __restrict__ bdec,
                                                  float* __restrict__ out_loc) {
    __shared__ unsigned long long zsp[NL * 32];  // [l][p] = (zs[2p][l], zs[2p+1][l])

    // transpose zs into shared: float view index l*64 + b
    {
        float* zf = (float*)zsp;
        for (int i = threadIdx.x; i < NB * NL; i += 256) {
            const int b = i >> 7;
            const int l = i & 127;
            zf[l * 64 + b] = g_zs[i];
        }
    }
    __syncthreads();

    const int tx = threadIdx.x & 127;   // column within block tile
    const int g  = threadIdx.x >> 7;    // 0: b 0..31, 1: b 32..63
    const int n0 = blockIdx.x * 256 + tx;
    const int n1 = n0 + 128;
    const int pbase = g * 16;

    unsigned long long acc0[16], acc1[16];
#pragma unroll
    for (int p = 0; p < 16; ++p) { acc0[p] = 0ull; acc1[p] = 0ull; }

    const float* w0 = Wd + n0;
    const float* w1 = Wd + n1;

#pragma unroll 8
    for (int l = 0; l < NL; ++l) {
        const float a = __ldg(w0 + (long long)l * NTOT);
        const float c = __ldg(w1 + (long long)l * NTOT);
        const unsigned long long wa = dup_f32(a);
        const unsigned long long wc = dup_f32(c);
        const unsigned long long* zrow = zsp + l * 32 + pbase;
#pragma unroll
        for (int p = 0; p < 16; ++p) {
            const unsigned long long z = zrow[p];
            acc0[p] = ffma2(z, wa, acc0[p]);
            acc1[p] = ffma2(z, wc, acc1[p]);
        }
    }

    const float bd0 = bdec[n0];
    const float bd1 = bdec[n1];
#pragma unroll
    for (int p = 0; p < 16; ++p) {
        const int b0 = (pbase + p) * 2;
        float2 v0 = *(float2*)&acc0[p];
        float2 v1 = *(float2*)&acc1[p];
        out_loc[(long long)b0 * NTOT + n0]       = v0.x + bd0;
        out_loc[(long long)(b0 + 1) * NTOT + n0] = v0.y + bd0;
        out_loc[(long long)b0 * NTOT + n1]       = v1.x + bd1;
        out_loc[(long long)(b0 + 1) * NTOT + n1] = v1.y + bd1;
    }
}

// ---------------------------------------------------------------------------
// K4: scale = softplus(log_scale)
// ---------------------------------------------------------------------------
__global__ void k4_scale(const float* __restrict__ log_scale, float* __restrict__ out) {
    const int f = threadIdx.x;
    if (f < NF) out[OFF_SCALE + f] = softplus_f(log_scale[f]);
}

// ---------------------------------------------------------------------------
// Launch
// ---------------------------------------------------------------------------
extern "C" void kernel_launch(void* const* d_in, const int* in_sizes, int n_in,
                              void* d_out, int out_size) {
    const float* x          = (const float*)d_in[0];
    const int*   label      = (const int*)d_in[1];
    const float* actionbias = (const float*)d_in[2];
    const float* W_mu       = (const float*)d_in[3];
    const float* b_mu       = (const float*)d_in[4];
    const float* W_std      = (const float*)d_in[5];
    const float* b_std      = (const float*)d_in[6];
    const float* W_dec      = (const float*)d_in[7];
    const float* b_dec      = (const float*)d_in[8];
    const float* log_scale  = (const float*)d_in[9];
    float* out = (float*)d_out;

    dim3 g1(NB, NSEG);
    k1_pool<<<g1, 256>>>(x);
    k2_encode<<<NB, NL>>>(W_mu, b_mu, W_std, b_std, actionbias, label, out);
    k3_decoder<<<NTOT / 256, 256>>>(W_dec, b_dec, out + OFF_LOC);
    k4_scale<<<1, NF>>>(log_scale, out);
}

// round 6
// speedup vs baseline: 1.0850x; 1.0850x over previous
#include <cuda_runtime.h>

// ---------------------------------------------------------------------------
// Problem constants
// ---------------------------------------------------------------------------
#define NB 64
#define NT 512
#define NF 1024
#define NL 128
#define NTOT (NT * NF)          // 524288 = T*F
#define NSEG 16                 // t-segments per batch in K1

// Output layout (flat concat in reference return order)
#define OFF_MU    0
#define OFF_STD   (NB * NL)                 // 8192
#define OFF_ZS    (2 * NB * NL)             // 16384
#define OFF_LOC   (3 * NB * NL)             // 24576
#define OFF_SCALE (3 * NB * NL + NB * NTOT) // 33579008

// K3 geometry
#define K3_NTILE 128
#define K3_SMEM  (64 * 1024 + 32 * 1024)    // W tile + z pairs = 98304 B

// ---------------------------------------------------------------------------
// Device scratch (no allocation allowed)
// ---------------------------------------------------------------------------
__device__ float g_hpart[NB * NSEG * NF];   // partial masked sums
__device__ float g_cntpart[NB * NSEG];      // partial mask counts
__device__ float g_zs[NB * NL];             // zs for decoder

// ---------------------------------------------------------------------------
// Helpers
// ---------------------------------------------------------------------------
__device__ __forceinline__ float softplus_f(float v) {
    return fmaxf(v, 0.0f) + log1pf(expf(-fabsf(v)));
}

__device__ __forceinline__ unsigned long long ffma2(unsigned long long a,
                                                    unsigned long long b,
                                                    unsigned long long c) {
    unsigned long long d;
    asm("fma.rn.f32x2 %0, %1, %2, %3;" : "=l"(d) : "l"(a), "l"(b), "l"(c));
    return d;
}

__device__ __forceinline__ unsigned long long dup_f32(float v) {
    unsigned long long r;
    asm("mov.b64 %0, {%1, %1};" : "=l"(r) : "f"(v));
    return r;
}

// Threefry-2x32, 20 rounds — exact JAX key schedule
__device__ __forceinline__ void tf2x32(unsigned int k0, unsigned int k1,
                                       unsigned int x0, unsigned int x1,
                                       unsigned int& o0, unsigned int& o1) {
    unsigned int ks2 = k0 ^ k1 ^ 0x1BD11BDAu;
    x0 += k0; x1 += k1;
#define TF_R(r) { x0 += x1; x1 = (x1 << (r)) | (x1 >> (32 - (r))); x1 ^= x0; }
    TF_R(13) TF_R(15) TF_R(26) TF_R(6)
    x0 += k1;  x1 += ks2 + 1u;
    TF_R(17) TF_R(29) TF_R(16) TF_R(24)
    x0 += ks2; x1 += k0 + 2u;
    TF_R(13) TF_R(15) TF_R(26) TF_R(6)
    x0 += k0;  x1 += k1 + 3u;
    TF_R(17) TF_R(29) TF_R(16) TF_R(24)
    x0 += k1;  x1 += ks2 + 4u;
    TF_R(13) TF_R(15) TF_R(26) TF_R(6)
    x0 += ks2; x1 += k0 + 5u;
#undef TF_R
    o0 = x0; o1 = x1;
}

// XLA f32 erf_inv (Giles polynomial)
__device__ __forceinline__ float erfinv_xla(float x) {
    float w = -log1pf(-x * x);
    float p;
    if (w < 5.0f) {
        w = w - 2.5f;
        p = 2.81022636e-08f;
        p = fmaf(p, w, 3.43273939e-07f);
        p = fmaf(p, w, -3.5233877e-06f);
        p = fmaf(p, w, -4.39150654e-06f);
        p = fmaf(p, w, 0.00021858087f);
        p = fmaf(p, w, -0.00125372503f);
        p = fmaf(p, w, -0.00417768164f);
        p = fmaf(p, w, 0.246640727f);
        p = fmaf(p, w, 1.50140941f);
    } else {
        w = sqrtf(w) - 3.0f;
        p = -0.000200214257f;
        p = fmaf(p, w, 0.000100950558f);
        p = fmaf(p, w, 0.00134934322f);
        p = fmaf(p, w, -0.00367342844f);
        p = fmaf(p, w, 0.00573950773f);
        p = fmaf(p, w, -0.0076224613f);
        p = fmaf(p, w, 0.00943887047f);
        p = fmaf(p, w, 1.00167406f);
        p = fmaf(p, w, 2.83297682f);
    }
    return p * x;
}

// ---------------------------------------------------------------------------
// K1: fused mask + masked sum-pool over t.  grid (NB, NSEG), 256 threads.
// float4 loads: one pass over x (134 MB), DRAM-bound.
// ---------------------------------------------------------------------------
__global__ __launch_bounds__(256) void k1_pool(const float* __restrict__ x) {
    const int b = blockIdx.x;
    const int s = blockIdx.y;
    const int warp = threadIdx.x >> 5;
    const int lane = threadIdx.x & 31;

    __shared__ float hsh[NF];
    __shared__ int cnt_sh;
    for (int i = threadIdx.x; i < NF; i += 256) hsh[i] = 0.0f;
    if (threadIdx.x == 0) cnt_sh = 0;
    __syncthreads();

    float4 acc[8];
#pragma unroll
    for (int j = 0; j < 8; ++j) acc[j] = make_float4(0.f, 0.f, 0.f, 0.f);
    int cnt = 0;

    const float* xb = x + ((long long)b * NT + s * (NT / NSEG)) * NF;
    const int rows = NT / NSEG;  // 32
    for (int r = warp; r < rows; r += 8) {
        const float4* row4 = (const float4*)(xb + (long long)r * NF);
        float4 v[8];
        float sum = 0.0f;
#pragma unroll
        for (int j = 0; j < 8; ++j) {
            v[j] = row4[lane + 32 * j];
            sum += (v[j].x + v[j].y) + (v[j].z + v[j].w);
        }
#pragma unroll
        for (int o = 16; o > 0; o >>= 1) sum += __shfl_xor_sync(0xffffffffu, sum, o);
        if (sum != 0.0f) {
            cnt++;
#pragma unroll
            for (int j = 0; j < 8; ++j) {
                acc[j].x += v[j].x; acc[j].y += v[j].y;
                acc[j].z += v[j].z; acc[j].w += v[j].w;
            }
        }
    }

#pragma unroll
    for (int j = 0; j < 8; ++j) {
        const int base = (lane + 32 * j) * 4;
        atomicAdd(&hsh[base + 0], acc[j].x);
        atomicAdd(&hsh[base + 1], acc[j].y);
        atomicAdd(&hsh[base + 2], acc[j].z);
        atomicAdd(&hsh[base + 3], acc[j].w);
    }
    if (lane == 0) atomicAdd(&cnt_sh, cnt);
    __syncthreads();

    const int part = b * NSEG + s;
    for (int i = threadIdx.x; i < NF; i += 256) g_hpart[part * NF + i] = hsh[i];
    if (threadIdx.x == 0) g_cntpart[part] = (float)cnt_sh;
}

// ---------------------------------------------------------------------------
// K2: encoder heads + threefry eps + zs.  grid NB, 512 threads.
// Thread (q, l): q = f-quarter, l = latent index. 4-way f-split for MLP.
// ---------------------------------------------------------------------------
__global__ __launch_bounds__(512) void k2_encode(
    const float* __restrict__ Wmu, const float* __restrict__ bmu,
    const float* __restrict__ Wstd, const float* __restrict__ bstd,
    const float* __restrict__ actionbias, const int* __restrict__ label,
    float* __restrict__ out) {
    const int b = blockIdx.x;
    const int l = threadIdx.x & 127;
    const int q = threadIdx.x >> 7;   // 0..3

    __shared__ float hsh[NF];
    __shared__ float red_mu[4][NL];
    __shared__ float red_sp[4][NL];
    __shared__ float inv_denom;

    for (int f = threadIdx.x; f < NF; f += 512) {
        float sum = 0.0f;
#pragma unroll
        for (int p = 0; p < NSEG; ++p) sum += g_hpart[(b * NSEG + p) * NF + f];
        hsh[f] = sum;
    }
    if (threadIdx.x == 0) {
        float c = 0.0f;
#pragma unroll
        for (int p = 0; p < NSEG; ++p) c += g_cntpart[b * NSEG + p];
        inv_denom = 1.0f / fmaxf(c, 1.0f);
    }
    __syncthreads();
    const float inv = inv_denom;
    for (int f = threadIdx.x; f < NF; f += 512) hsh[f] *= inv;
    __syncthreads();

    float mu = 0.0f;
    float sp = 0.0f;
    const int f0 = q * (NF / 4);
#pragma unroll 8
    for (int f = f0; f < f0 + NF / 4; ++f) {
        const float hv = hsh[f];
        mu = fmaf(hv, Wmu[f * NL + l], mu);
        sp = fmaf(hv, Wstd[f * NL + l], sp);
    }
    red_mu[q][l] = mu;
    red_sp[q][l] = sp;
    __syncthreads();

    if (q == 0) {
        mu = ((red_mu[0][l] + red_mu[1][l]) + (red_mu[2][l] + red_mu[3][l])) + bmu[l];
        sp = ((red_sp[0][l] + red_sp[1][l]) + (red_sp[2][l] + red_sp[3][l])) + bstd[l];
        const float stdv = softplus_f(sp);

        // eps: partitionable threefry, fold_in(key(0),1), bits = o0 ^ o1
        unsigned int nk0, nk1;
        tf2x32(0u, 0u, 0u, 1u, nk0, nk1);
        const int idx = b * NL + l;
        unsigned int o0, o1;
        tf2x32(nk0, nk1, 0u, (unsigned int)idx, o0, o1);
        const unsigned int bits = o0 ^ o1;
        const float f01 = __uint_as_float(0x3F800000u | (bits >> 9)) - 1.0f;
        float u = fmaf(f01, 2.0f, -0.99999994f);
        u = fmaxf(u, -0.99999994f);
        const float eps = 1.41421356237309515f * erfinv_xla(u);

        const float zs = mu + stdv * eps + actionbias[label[b] * NL + l];

        out[OFF_MU + idx]  = mu;
        out[OFF_STD + idx] = stdv;
        out[OFF_ZS + idx]  = zs;
        g_zs[idx] = zs;
    }
}

// ---------------------------------------------------------------------------
// K3: decoder GEMM  loc[b,n] = sum_l zs[b,l]*W_dec[l,n] + b_dec[n]
// Smem-tiled: block = 64 b x 128 n. W tile staged once (DRAM read 1x total).
// Thread = 2 adjacent n x 16 b (8 packed b-pairs). fma.rn.f32x2 throughout.
// 96 KB dynamic smem -> 2 blocks/SM. FMA-pipe bound.
// ---------------------------------------------------------------------------
__global__ __launch_bounds__(256) void k3_decoder(const float* __restrict__ Wd,
                                                  const float* __restrict__ bdec,
                                                  float* __restrict__ out_loc) {
    extern __shared__ char sm[];
    float* Wt = (float*)sm;                                        // [128 l][128 n]
    unsigned long long* zsp = (unsigned long long*)(sm + 65536);   // [128 l][32 p]

    const long long nbase = (long long)blockIdx.x * K3_NTILE;

    // stage z pairs: zsp[l*32 + p] = (zs[2p][l], zs[2p+1][l])
    {
        float* zf = (float*)zsp;
        for (int i = threadIdx.x; i < NB * NL; i += 256) {
            const int b = i >> 7;
            const int l = i & 127;
            zf[l * 64 + b] = g_zs[i];
        }
    }
    // stage W tile: Wt[l][n] = Wd[l*NTOT + nbase + n], float4 coalesced
    for (int i = threadIdx.x; i < (NL * K3_NTILE) / 4; i += 256) {
        const int l = i >> 5;        // 32 float4 per l-row
        const int c = i & 31;
        ((float4*)Wt)[i] = *(const float4*)(Wd + (long long)l * NTOT + nbase + c * 4);
    }
    __syncthreads();

    const int nx = threadIdx.x & 63;    // 64 threads cover 128 n (2 adjacent each)
    const int bg = threadIdx.x >> 6;    // 4 b-groups of 16 b (8 pairs)
    const int n0 = nx * 2;

    unsigned long long acc0[8], acc1[8];
#pragma unroll
    for (int p = 0; p < 8; ++p) { acc0[p] = 0ull; acc1[p] = 0ull; }

    const float* wrow = Wt + n0;
    const unsigned long long* zbase = zsp + bg * 8;

#pragma unroll 4
    for (int l = 0; l < NL; ++l) {
        const float2 w = *(const float2*)(wrow + l * K3_NTILE);
        const unsigned long long wa = dup_f32(w.x);
        const unsigned long long wc = dup_f32(w.y);
        const unsigned long long* z = zbase + l * 32;
#pragma unroll
        for (int p = 0; p < 8; ++p) {
            const unsigned long long zp = z[p];
            acc0[p] = ffma2(zp, wa, acc0[p]);
            acc1[p] = ffma2(zp, wc, acc1[p]);
        }
    }

    const float bd0 = bdec[nbase + n0];
    const float bd1 = bdec[nbase + n0 + 1];
#pragma unroll
    for (int p = 0; p < 8; ++p) {
        const int b0 = (bg * 8 + p) * 2;
        const float2 a = *(const float2*)&acc0[p];  // (b0@n0, b1@n0)
        const float2 c = *(const float2*)&acc1[p];  // (b0@n1, b1@n1)
        float2 r0, r1;
        r0.x = a.x + bd0; r0.y = c.x + bd1;
        r1.x = a.y + bd0; r1.y = c.y + bd1;
        *(float2*)(out_loc + (long long)b0 * NTOT + nbase + n0)       = r0;
        *(float2*)(out_loc + (long long)(b0 + 1) * NTOT + nbase + n0) = r1;
    }
}

// ---------------------------------------------------------------------------
// K4: scale = softplus(log_scale)
// ---------------------------------------------------------------------------
__global__ void k4_scale(const float* __restrict__ log_scale, float* __restrict__ out) {
    const int f = threadIdx.x;
    if (f < NF) out[OFF_SCALE + f] = softplus_f(log_scale[f]);
}

// ---------------------------------------------------------------------------
// Launch
// ---------------------------------------------------------------------------
extern "C" void kernel_launch(void* const* d_in, const int* in_sizes, int n_in,
                              void* d_out, int out_size) {
    const float* x          = (const float*)d_in[0];
    const int*   label      = (const int*)d_in[1];
    const float* actionbias = (const float*)d_in[2];
    const float* W_mu       = (const float*)d_in[3];
    const float* b_mu       = (const float*)d_in[4];
    const float* W_std      = (const float*)d_in[5];
    const float* b_std      = (const float*)d_in[6];
    const float* W_dec      = (const float*)d_in[7];
    const float* b_dec      = (const float*)d_in[8];
    const float* log_scale  = (const float*)d_in[9];
    float* out = (float*)d_out;

    static int smem_set = 0;
    if (!smem_set) {
        cudaFuncSetAttribute(k3_decoder, cudaFuncAttributeMaxDynamicSharedMemorySize,
                             K3_SMEM);
        smem_set = 1;
    }

    dim3 g1(NB, NSEG);
    k1_pool<<<g1, 256>>>(x);
    k2_encode<<<NB, 512>>>(W_mu, b_mu, W_std, b_std, actionbias, label, out);
    k3_decoder<<<NTOT / K3_NTILE, 256, K3_SMEM>>>(W_dec, b_dec, out + OFF_LOC);
    k4_scale<<<1, NF>>>(log_scale, out);
}

// round 8
// speedup vs baseline: 1.3820x; 1.2737x over previous
#include <cuda_runtime.h>
#include <cuda_bf16.h>
#include <cstdint>

// ---------------------------------------------------------------------------
// Problem constants
// ---------------------------------------------------------------------------
#define NB 64
#define NT 512
#define NF 1024
#define NL 128
#define NTOT (NT * NF)          // 524288 = T*F
#define NSEG 16                 // t-segments per batch in K1

// Output layout (flat concat in reference return order)
#define OFF_MU    0
#define OFF_STD   (NB * NL)                 // 8192
#define OFF_ZS    (2 * NB * NL)             // 16384
#define OFF_LOC   (3 * NB * NL)             // 24576
#define OFF_SCALE (3 * NB * NL + NB * NTOT) // 33579008

// ---------------------------------------------------------------------------
// Device scratch (no allocation allowed)
// ---------------------------------------------------------------------------
__device__ float g_hpart[NB * NSEG * NF];   // partial masked sums
__device__ float g_cntpart[NB * NSEG];      // partial mask counts
__device__ float g_zs[NB * NL];             // zs for decoder

// ---------------------------------------------------------------------------
// Small helpers
// ---------------------------------------------------------------------------
__device__ __forceinline__ float softplus_f(float v) {
    return fmaxf(v, 0.0f) + log1pf(expf(-fabsf(v)));
}

// Threefry-2x32, 20 rounds — exact JAX key schedule
__device__ __forceinline__ void tf2x32(unsigned int k0, unsigned int k1,
                                       unsigned int x0, unsigned int x1,
                                       unsigned int& o0, unsigned int& o1) {
    unsigned int ks2 = k0 ^ k1 ^ 0x1BD11BDAu;
    x0 += k0; x1 += k1;
#define TF_R(r) { x0 += x1; x1 = (x1 << (r)) | (x1 >> (32 - (r))); x1 ^= x0; }
    TF_R(13) TF_R(15) TF_R(26) TF_R(6)
    x0 += k1;  x1 += ks2 + 1u;
    TF_R(17) TF_R(29) TF_R(16) TF_R(24)
    x0 += ks2; x1 += k0 + 2u;
    TF_R(13) TF_R(15) TF_R(26) TF_R(6)
    x0 += k0;  x1 += k1 + 3u;
    TF_R(17) TF_R(29) TF_R(16) TF_R(24)
    x0 += k1;  x1 += ks2 + 4u;
    TF_R(13) TF_R(15) TF_R(26) TF_R(6)
    x0 += ks2; x1 += k0 + 5u;
#undef TF_R
    o0 = x0; o1 = x1;
}

// XLA f32 erf_inv (Giles polynomial)
__device__ __forceinline__ float erfinv_xla(float x) {
    float w = -log1pf(-x * x);
    float p;
    if (w < 5.0f) {
        w = w - 2.5f;
        p = 2.81022636e-08f;
        p = fmaf(p, w, 3.43273939e-07f);
        p = fmaf(p, w, -3.5233877e-06f);
        p = fmaf(p, w, -4.39150654e-06f);
        p = fmaf(p, w, 0.00021858087f);
        p = fmaf(p, w, -0.00125372503f);
        p = fmaf(p, w, -0.00417768164f);
        p = fmaf(p, w, 0.246640727f);
        p = fmaf(p, w, 1.50140941f);
    } else {
        w = sqrtf(w) - 3.0f;
        p = -0.000200214257f;
        p = fmaf(p, w, 0.000100950558f);
        p = fmaf(p, w, 0.00134934322f);
        p = fmaf(p, w, -0.00367342844f);
        p = fmaf(p, w, 0.00573950773f);
        p = fmaf(p, w, -0.0076224613f);
        p = fmaf(p, w, 0.00943887047f);
        p = fmaf(p, w, 1.00167406f);
        p = fmaf(p, w, 2.83297682f);
    }
    return p * x;
}

// ---------------------------------------------------------------------------
// mma.sync / ldmatrix helpers (portable sm_80+ PTX, assembles on plain sm_103)
// ---------------------------------------------------------------------------
__device__ __forceinline__ uint32_t smem_to_u32(const void* smem_ptr) {
    uint32_t addr;
    asm("{ .reg .u64 tmp; cvta.to.shared.u64 tmp, %1; cvt.u32.u64 %0, tmp; }"
        : "=r"(addr) : "l"(smem_ptr));
    return addr;
}

__device__ __forceinline__ void ldsm_x4(uint32_t* r, uint32_t addr) {
    asm volatile("ldmatrix.sync.aligned.m8n8.x4.shared.b16 {%0,%1,%2,%3}, [%4];"
        : "=r"(r[0]), "=r"(r[1]), "=r"(r[2]), "=r"(r[3]) : "r"(addr));
}

__device__ __forceinline__ void ldsm_x2_trans(uint32_t* r, uint32_t addr) {
    asm volatile("ldmatrix.sync.aligned.m8n8.x2.trans.shared.b16 {%0,%1}, [%2];"
        : "=r"(r[0]), "=r"(r[1]) : "r"(addr));
}

__device__ __forceinline__ void mma_bf16(float* d, const uint32_t* a, const uint32_t* b) {
    asm volatile(
        "mma.sync.aligned.m16n8k16.row.col.f32.bf16.bf16.f32 "
        "{%0,%1,%2,%3}, {%4,%5,%6,%7}, {%8,%9}, {%0,%1,%2,%3};"
        : "+f"(d[0]), "+f"(d[1]), "+f"(d[2]), "+f"(d[3])
        : "r"(a[0]), "r"(a[1]), "r"(a[2]), "r"(a[3]), "r"(b[0]), "r"(b[1]));
}

// ---------------------------------------------------------------------------
// K1: fused mask + masked sum-pool over t.  grid (NB, NSEG), 256 threads.
// ---------------------------------------------------------------------------
__global__ __launch_bounds__(256) void k1_pool(const float* __restrict__ x) {
    const int b = blockIdx.x;
    const int s = blockIdx.y;
    const int warp = threadIdx.x >> 5;
    const int lane = threadIdx.x & 31;

    __shared__ float hsh[NF];
    __shared__ int cnt_sh;
    for (int i = threadIdx.x; i < NF; i += 256) hsh[i] = 0.0f;
    if (threadIdx.x == 0) cnt_sh = 0;
    __syncthreads();

    float4 acc[8];
#pragma unroll
    for (int j = 0; j < 8; ++j) acc[j] = make_float4(0.f, 0.f, 0.f, 0.f);
    int cnt = 0;

    const float* xb = x + ((long long)b * NT + s * (NT / NSEG)) * NF;
    const int rows = NT / NSEG;  // 32
    for (int r = warp; r < rows; r += 8) {
        const float4* row4 = (const float4*)(xb + (long long)r * NF);
        float4 v[8];
        float sum = 0.0f;
#pragma unroll
        for (int j = 0; j < 8; ++j) {
            v[j] = row4[lane + 32 * j];
            sum += (v[j].x + v[j].y) + (v[j].z + v[j].w);
        }
#pragma unroll
        for (int o = 16; o > 0; o >>= 1) sum += __shfl_xor_sync(0xffffffffu, sum, o);
        if (sum != 0.0f) {
            cnt++;
#pragma unroll
            for (int j = 0; j < 8; ++j) {
                acc[j].x += v[j].x; acc[j].y += v[j].y;
                acc[j].z += v[j].z; acc[j].w += v[j].w;
            }
        }
    }

#pragma unroll
    for (int j = 0; j < 8; ++j) {
        const int base = (lane + 32 * j) * 4;
        atomicAdd(&hsh[base + 0], acc[j].x);
        atomicAdd(&hsh[base + 1], acc[j].y);
        atomicAdd(&hsh[base + 2], acc[j].z);
        atomicAdd(&hsh[base + 3], acc[j].w);
    }
    if (lane == 0) atomicAdd(&cnt_sh, cnt);
    __syncthreads();

    const int part = b * NSEG + s;
    for (int i = threadIdx.x; i < NF; i += 256) g_hpart[part * NF + i] = hsh[i];
    if (threadIdx.x == 0) g_cntpart[part] = (float)cnt_sh;
}

// ---------------------------------------------------------------------------
// K2: encoder heads + threefry eps + zs.  grid NB, 512 threads.
// ---------------------------------------------------------------------------
__global__ __launch_bounds__(512) void k2_encode(
    const float* __restrict__ Wmu, const float* __restrict__ bmu,
    const float* __restrict__ Wstd, const float* __restrict__ bstd,
    const float* __restrict__ actionbias, const int* __restrict__ label,
    float* __restrict__ out) {
    const int b = blockIdx.x;
    const int l = threadIdx.x & 127;
    const int q = threadIdx.x >> 7;   // 0..3

    __shared__ float hsh[NF];
    __shared__ float red_mu[4][NL];
    __shared__ float red_sp[4][NL];
    __shared__ float inv_denom;

    for (int f = threadIdx.x; f < NF; f += 512) {
        float sum = 0.0f;
#pragma unroll
        for (int p = 0; p < NSEG; ++p) sum += g_hpart[(b * NSEG + p) * NF + f];
        hsh[f] = sum;
    }
    if (threadIdx.x == 0) {
        float c = 0.0f;
#pragma unroll
        for (int p = 0; p < NSEG; ++p) c += g_cntpart[b * NSEG + p];
        inv_denom = 1.0f / fmaxf(c, 1.0f);
    }
    __syncthreads();
    const float inv = inv_denom;
    for (int f = threadIdx.x; f < NF; f += 512) hsh[f] *= inv;
    __syncthreads();

    float mu = 0.0f;
    float sp = 0.0f;
    const int f0 = q * (NF / 4);
#pragma unroll 8
    for (int f = f0; f < f0 + NF / 4; ++f) {
        const float hv = hsh[f];
        mu = fmaf(hv, Wmu[f * NL + l], mu);
        sp = fmaf(hv, Wstd[f * NL + l], sp);
    }
    red_mu[q][l] = mu;
    red_sp[q][l] = sp;
    __syncthreads();

    if (q == 0) {
        mu = ((red_mu[0][l] + red_mu[1][l]) + (red_mu[2][l] + red_mu[3][l])) + bmu[l];
        sp = ((red_sp[0][l] + red_sp[1][l]) + (red_sp[2][l] + red_sp[3][l])) + bstd[l];
        const float stdv = softplus_f(sp);

        unsigned int nk0, nk1;
        tf2x32(0u, 0u, 0u, 1u, nk0, nk1);
        const int idx = b * NL + l;
        unsigned int o0, o1;
        tf2x32(nk0, nk1, 0u, (unsigned int)idx, o0, o1);
        const unsigned int bits = o0 ^ o1;
        const float f01 = __uint_as_float(0x3F800000u | (bits >> 9)) - 1.0f;
        float u = fmaf(f01, 2.0f, -0.99999994f);
        u = fmaxf(u, -0.99999994f);
        const float eps = 1.41421356237309515f * erfinv_xla(u);

        const float zs = mu + stdv * eps + actionbias[label[b] * NL + l];

        out[OFF_MU + idx]  = mu;
        out[OFF_STD + idx] = stdv;
        out[OFF_ZS + idx]  = zs;
        g_zs[idx] = zs;
    }
}

// ---------------------------------------------------------------------------
// K3: decoder GEMM via mma.sync bf16 split (hi/lo), persistent 148 blocks.
//   loc[b][n] = sum_l zs[b][l] * W[l][n] + bdec[n]
//   M = b (64), N = n-tile (128), K = l (128).
//   A = zs in smem [b][l] rows padded to 272B, read with ldmatrix.x4.
//   W staged per tile in smem [l][n] rows padded to 272B (double-buffered,
//   hi+lo bf16), read with ldmatrix.x2.trans.
//   3 passes: Ahi*Whi + Alo*Whi + Ahi*Wlo  (f32 accum, rel err ~5e-6).
// ---------------------------------------------------------------------------
#define K3_GRID   148
#define K3_TILES  (NTOT / 128)   // 4096
#define ROWB      272            // padded row stride (17 x 16B)

#define ZS_H   0
#define ZS_L   (64 * ROWB)                 // 17408
#define W_BASE (2 * 64 * ROWB)             // 34816
#define WOFF(p, h) (W_BASE + ((p) * 2 + (h)) * (128 * ROWB))
#define K3_SMEM (W_BASE + 4 * 128 * ROWB)  // 174080

__global__ __launch_bounds__(256, 1) void k3_decoder_mma(const float* __restrict__ Wd,
                                                         const float* __restrict__ bdec,
                                                         float* __restrict__ out_loc) {
    extern __shared__ char smem[];
    const uint32_t sb = smem_to_u32(smem);
    const int tid  = threadIdx.x;
    const int wid  = tid >> 5;
    const int lane = tid & 31;
    const int nl   = tid & 127;   // n within tile for staging
    const int lsel = tid >> 7;    // 0/1: even/odd l for staging

    // --- prologue: zs hi/lo into smem [b][l] (built once) ---
    for (int i = tid; i < NB * NL; i += 256) {
        const int b = i >> 7;
        const int l = i & 127;
        const float v = g_zs[i];
        const __nv_bfloat16 hi = __float2bfloat16(v);
        const __nv_bfloat16 lo = __float2bfloat16(v - __bfloat162float(hi));
        *(__nv_bfloat16*)(smem + ZS_H + b * ROWB + l * 2) = hi;
        *(__nv_bfloat16*)(smem + ZS_L + b * ROWB + l * 2) = lo;
    }

    // --- stage first W tile into buffer 0 ---
    {
        const long long nb0 = (long long)blockIdx.x * 128;
        const float* src = Wd + nb0 + nl;
        char* dH = smem + WOFF(0, 0) + nl * 2;
        char* dL = smem + WOFF(0, 1) + nl * 2;
#pragma unroll 8
        for (int j = 0; j < 64; ++j) {
            const int l = 2 * j + lsel;
            const float v = __ldg(src + (long long)l * NTOT);
            const __nv_bfloat16 hi = __float2bfloat16(v);
            const __nv_bfloat16 lo = __float2bfloat16(v - __bfloat162float(hi));
            *(__nv_bfloat16*)(dH + l * ROWB) = hi;
            *(__nv_bfloat16*)(dL + l * ROWB) = lo;
        }
    }
    __syncthreads();

    int i = 0;
    for (int tile = blockIdx.x; tile < K3_TILES; tile += K3_GRID, ++i) {
        const int p = i & 1;

        // --- stage next tile into the other buffer (overlaps with compute) ---
        const int ntile = tile + K3_GRID;
        if (ntile < K3_TILES) {
            const long long nb2 = (long long)ntile * 128;
            const float* src = Wd + nb2 + nl;
            char* dH = smem + WOFF(p ^ 1, 0) + nl * 2;
            char* dL = smem + WOFF(p ^ 1, 1) + nl * 2;
#pragma unroll 8
            for (int j = 0; j < 64; ++j) {
                const int l = 2 * j + lsel;
                const float v = __ldg(src + (long long)l * NTOT);
                const __nv_bfloat16 hi = __float2bfloat16(v);
                const __nv_bfloat16 lo = __float2bfloat16(v - __bfloat162float(hi));
                *(__nv_bfloat16*)(dH + l * ROWB) = hi;
                *(__nv_bfloat16*)(dL + l * ROWB) = lo;
            }
        }

        // --- compute this tile ---
        const long long nbase = (long long)tile * 128;
        const uint32_t wH = sb + WOFF(p, 0);
        const uint32_t wL = sb + WOFF(p, 1);

        float acc[4][2][4];
#pragma unroll
        for (int mt = 0; mt < 4; ++mt)
#pragma unroll
            for (int nt = 0; nt < 2; ++nt)
#pragma unroll
                for (int r = 0; r < 4; ++r) acc[mt][nt][r] = 0.0f;

        const uint32_t arow = (uint32_t)(lane & 15) * ROWB + (uint32_t)(lane >> 4) * 16;
        const uint32_t brow = (uint32_t)(lane & 15) * ROWB + (uint32_t)wid * 32;

#pragma unroll
        for (int ks = 0; ks < 8; ++ks) {
            uint32_t bh[2][2], bl[2][2];
#pragma unroll
            for (int nt = 0; nt < 2; ++nt) {
                const uint32_t ba = (uint32_t)(16 * ks) * ROWB + brow + (uint32_t)nt * 16;
                ldsm_x2_trans(bh[nt], wH + ba);
                ldsm_x2_trans(bl[nt], wL + ba);
            }
#pragma unroll
            for (int mt = 0; mt < 4; ++mt) {
                uint32_t ah[4], al[4];
                const uint32_t aa = (uint32_t)(16 * mt) * ROWB + arow + (uint32_t)(ks * 32);
                ldsm_x4(ah, sb + ZS_H + aa);
                ldsm_x4(al, sb + ZS_L + aa);
#pragma unroll
                for (int nt = 0; nt < 2; ++nt) {
                    mma_bf16(acc[mt][nt], ah, bh[nt]);
                    mma_bf16(acc[mt][nt], al, bh[nt]);
                    mma_bf16(acc[mt][nt], ah, bl[nt]);
                }
            }
        }

        // --- epilogue: coalesced float2 stores ---
#pragma unroll
        for (int nt = 0; nt < 2; ++nt) {
            const long long n = nbase + wid * 16 + nt * 8 + 2 * (lane & 3);
            const float2 bd = *(const float2*)(bdec + n);
#pragma unroll
            for (int mt = 0; mt < 4; ++mt) {
                const int b = mt * 16 + (lane >> 2);
                float2 v0, v1;
                v0.x = acc[mt][nt][0] + bd.x;  v0.y = acc[mt][nt][1] + bd.y;
                v1.x = acc[mt][nt][2] + bd.x;  v1.y = acc[mt][nt][3] + bd.y;
                *(float2*)(out_loc + (long long)b * NTOT + n)       = v0;
                *(float2*)(out_loc + (long long)(b + 8) * NTOT + n) = v1;
            }
        }
        __syncthreads();
    }
}

// ---------------------------------------------------------------------------
// K4: scale = softplus(log_scale)
// ---------------------------------------------------------------------------
__global__ void k4_scale(const float* __restrict__ log_scale, float* __restrict__ out) {
    const int f = threadIdx.x;
    if (f < NF) out[OFF_SCALE + f] = softplus_f(log_scale[f]);
}

// ---------------------------------------------------------------------------
// Launch
// ---------------------------------------------------------------------------
extern "C" void kernel_launch(void* const* d_in, const int* in_sizes, int n_in,
                              void* d_out, int out_size) {
    const float* x          = (const float*)d_in[0];
    const int*   label      = (const int*)d_in[1];
    const float* actionbias = (const float*)d_in[2];
    const float* W_mu       = (const float*)d_in[3];
    const float* b_mu       = (const float*)d_in[4];
    const float* W_std      = (const float*)d_in[5];
    const float* b_std      = (const float*)d_in[6];
    const float* W_dec      = (const float*)d_in[7];
    const float* b_dec      = (const float*)d_in[8];
    const float* log_scale  = (const float*)d_in[9];
    float* out = (float*)d_out;

    static int smem_set = 0;
    if (!smem_set) {
        cudaFuncSetAttribute(k3_decoder_mma, cudaFuncAttributeMaxDynamicSharedMemorySize,
                             K3_SMEM);
        smem_set = 1;
    }

    dim3 g1(NB, NSEG);
    k1_pool<<<g1, 256>>>(x);
    k2_encode<<<NB, 512>>>(W_mu, b_mu, W_std, b_std, actionbias, label, out);
    k3_decoder_mma<<<K3_GRID, 256, K3_SMEM>>>(W_dec, b_dec, out + OFF_LOC);
    k4_scale<<<1, NF>>>(log_scale, out);
}

// round 9
// speedup vs baseline: 2.2257x; 1.6105x over previous
#include <cuda_runtime.h>
#include <cuda_bf16.h>
#include <cstdint>

// ---------------------------------------------------------------------------
// Problem constants
// ---------------------------------------------------------------------------
#define NB 64
#define NT 512
#define NF 1024
#define NL 128
#define NTOT (NT * NF)          // 524288 = T*F
#define NSEG 16                 // t-segments per batch in K1

// Output layout (flat concat in reference return order)
#define OFF_MU    0
#define OFF_STD   (NB * NL)                 // 8192
#define OFF_ZS    (2 * NB * NL)             // 16384
#define OFF_LOC   (3 * NB * NL)             // 24576
#define OFF_SCALE (3 * NB * NL + NB * NTOT) // 33579008

// ---------------------------------------------------------------------------
// Device scratch (no allocation allowed)
// ---------------------------------------------------------------------------
__device__ float g_hpart[NB * NSEG * NF];   // partial masked sums
__device__ float g_cntpart[NB * NSEG];      // partial mask counts
__device__ float g_zs[NB * NL];             // zs for decoder

// ---------------------------------------------------------------------------
// Small helpers
// ---------------------------------------------------------------------------
__device__ __forceinline__ float softplus_f(float v) {
    return fmaxf(v, 0.0f) + log1pf(expf(-fabsf(v)));
}

// Threefry-2x32, 20 rounds — exact JAX key schedule
__device__ __forceinline__ void tf2x32(unsigned int k0, unsigned int k1,
                                       unsigned int x0, unsigned int x1,
                                       unsigned int& o0, unsigned int& o1) {
    unsigned int ks2 = k0 ^ k1 ^ 0x1BD11BDAu;
    x0 += k0; x1 += k1;
#define TF_R(r) { x0 += x1; x1 = (x1 << (r)) | (x1 >> (32 - (r))); x1 ^= x0; }
    TF_R(13) TF_R(15) TF_R(26) TF_R(6)
    x0 += k1;  x1 += ks2 + 1u;
    TF_R(17) TF_R(29) TF_R(16) TF_R(24)
    x0 += ks2; x1 += k0 + 2u;
    TF_R(13) TF_R(15) TF_R(26) TF_R(6)
    x0 += k0;  x1 += k1 + 3u;
    TF_R(17) TF_R(29) TF_R(16) TF_R(24)
    x0 += k1;  x1 += ks2 + 4u;
    TF_R(13) TF_R(15) TF_R(26) TF_R(6)
    x0 += ks2; x1 += k0 + 5u;
#undef TF_R
    o0 = x0; o1 = x1;
}

// XLA f32 erf_inv (Giles polynomial)
__device__ __forceinline__ float erfinv_xla(float x) {
    float w = -log1pf(-x * x);
    float p;
    if (w < 5.0f) {
        w = w - 2.5f;
        p = 2.81022636e-08f;
        p = fmaf(p, w, 3.43273939e-07f);
        p = fmaf(p, w, -3.5233877e-06f);
        p = fmaf(p, w, -4.39150654e-06f);
        p = fmaf(p, w, 0.00021858087f);
        p = fmaf(p, w, -0.00125372503f);
        p = fmaf(p, w, -0.00417768164f);
        p = fmaf(p, w, 0.246640727f);
        p = fmaf(p, w, 1.50140941f);
    } else {
        w = sqrtf(w) - 3.0f;
        p = -0.000200214257f;
        p = fmaf(p, w, 0.000100950558f);
        p = fmaf(p, w, 0.00134934322f);
        p = fmaf(p, w, -0.00367342844f);
        p = fmaf(p, w, 0.00573950773f);
        p = fmaf(p, w, -0.0076224613f);
        p = fmaf(p, w, 0.00943887047f);
        p = fmaf(p, w, 1.00167406f);
        p = fmaf(p, w, 2.83297682f);
    }
    return p * x;
}

// ---------------------------------------------------------------------------
// mma.sync / ldmatrix helpers (portable sm_80+ PTX, assembles on plain sm_103)
// ---------------------------------------------------------------------------
__device__ __forceinline__ uint32_t smem_to_u32(const void* smem_ptr) {
    uint32_t addr;
    asm("{ .reg .u64 tmp; cvta.to.shared.u64 tmp, %1; cvt.u32.u64 %0, tmp; }"
        : "=r"(addr) : "l"(smem_ptr));
    return addr;
}

__device__ __forceinline__ void ldsm_x4(uint32_t* r, uint32_t addr) {
    asm volatile("ldmatrix.sync.aligned.m8n8.x4.shared.b16 {%0,%1,%2,%3}, [%4];"
        : "=r"(r[0]), "=r"(r[1]), "=r"(r[2]), "=r"(r[3]) : "r"(addr));
}

__device__ __forceinline__ void ldsm_x2_trans(uint32_t* r, uint32_t addr) {
    asm volatile("ldmatrix.sync.aligned.m8n8.x2.trans.shared.b16 {%0,%1}, [%2];"
        : "=r"(r[0]), "=r"(r[1]) : "r"(addr));
}

__device__ __forceinline__ void mma_bf16(float* d, const uint32_t* a, const uint32_t* b) {
    asm volatile(
        "mma.sync.aligned.m16n8k16.row.col.f32.bf16.bf16.f32 "
        "{%0,%1,%2,%3}, {%4,%5,%6,%7}, {%8,%9}, {%0,%1,%2,%3};"
        : "+f"(d[0]), "+f"(d[1]), "+f"(d[2]), "+f"(d[3])
        : "r"(a[0]), "r"(a[1]), "r"(a[2]), "r"(a[3]), "r"(b[0]), "r"(b[1]));
}

// pack two floats to bf16x2 (x -> low), return hi word + exact residuals
__device__ __forceinline__ uint32_t pack_bf16x2(float x, float y) {
    __nv_bfloat162 h = __float22bfloat162_rn(make_float2(x, y));
    return *(uint32_t*)&h;
}

// ---------------------------------------------------------------------------
// K1: fused mask + masked sum-pool over t.  grid (NB, NSEG), 256 threads.
// ---------------------------------------------------------------------------
__global__ __launch_bounds__(256) void k1_pool(const float* __restrict__ x) {
    const int b = blockIdx.x;
    const int s = blockIdx.y;
    const int warp = threadIdx.x >> 5;
    const int lane = threadIdx.x & 31;

    __shared__ float hsh[NF];
    __shared__ int cnt_sh;
    for (int i = threadIdx.x; i < NF; i += 256) hsh[i] = 0.0f;
    if (threadIdx.x == 0) cnt_sh = 0;
    __syncthreads();

    float4 acc[8];
#pragma unroll
    for (int j = 0; j < 8; ++j) acc[j] = make_float4(0.f, 0.f, 0.f, 0.f);
    int cnt = 0;

    const float* xb = x + ((long long)b * NT + s * (NT / NSEG)) * NF;
    const int rows = NT / NSEG;  // 32
    for (int r = warp; r < rows; r += 8) {
        const float4* row4 = (const float4*)(xb + (long long)r * NF);
        float4 v[8];
        float sum = 0.0f;
#pragma unroll
        for (int j = 0; j < 8; ++j) {
            v[j] = row4[lane + 32 * j];
            sum += (v[j].x + v[j].y) + (v[j].z + v[j].w);
        }
#pragma unroll
        for (int o = 16; o > 0; o >>= 1) sum += __shfl_xor_sync(0xffffffffu, sum, o);
        if (sum != 0.0f) {
            cnt++;
#pragma unroll
            for (int j = 0; j < 8; ++j) {
                acc[j].x += v[j].x; acc[j].y += v[j].y;
                acc[j].z += v[j].z; acc[j].w += v[j].w;
            }
        }
    }

#pragma unroll
    for (int j = 0; j < 8; ++j) {
        const int base = (lane + 32 * j) * 4;
        atomicAdd(&hsh[base + 0], acc[j].x);
        atomicAdd(&hsh[base + 1], acc[j].y);
        atomicAdd(&hsh[base + 2], acc[j].z);
        atomicAdd(&hsh[base + 3], acc[j].w);
    }
    if (lane == 0) atomicAdd(&cnt_sh, cnt);
    __syncthreads();

    const int part = b * NSEG + s;
    for (int i = threadIdx.x; i < NF; i += 256) g_hpart[part * NF + i] = hsh[i];
    if (threadIdx.x == 0) g_cntpart[part] = (float)cnt_sh;
}

// ---------------------------------------------------------------------------
// K2: encoder heads + threefry eps + zs.  grid NB+1, 512 threads.
// Extra block (blockIdx.x == NB) writes scale = softplus(log_scale).
// ---------------------------------------------------------------------------
__global__ __launch_bounds__(512) void k2_encode(
    const float* __restrict__ Wmu, const float* __restrict__ bmu,
    const float* __restrict__ Wstd, const float* __restrict__ bstd,
    const float* __restrict__ actionbias, const int* __restrict__ label,
    const float* __restrict__ log_scale,
    float* __restrict__ out) {
    if (blockIdx.x == NB) {
        for (int f = threadIdx.x; f < NF; f += 512)
            out[OFF_SCALE + f] = softplus_f(log_scale[f]);
        return;
    }
    const int b = blockIdx.x;
    const int l = threadIdx.x & 127;
    const int q = threadIdx.x >> 7;   // 0..3

    __shared__ float hsh[NF];
    __shared__ float red_mu[4][NL];
    __shared__ float red_sp[4][NL];
    __shared__ float inv_denom;

    for (int f = threadIdx.x; f < NF; f += 512) {
        float sum = 0.0f;
#pragma unroll
        for (int p = 0; p < NSEG; ++p) sum += g_hpart[(b * NSEG + p) * NF + f];
        hsh[f] = sum;
    }
    if (threadIdx.x == 0) {
        float c = 0.0f;
#pragma unroll
        for (int p = 0; p < NSEG; ++p) c += g_cntpart[b * NSEG + p];
        inv_denom = 1.0f / fmaxf(c, 1.0f);
    }
    __syncthreads();
    const float inv = inv_denom;
    for (int f = threadIdx.x; f < NF; f += 512) hsh[f] *= inv;
    __syncthreads();

    float mu = 0.0f;
    float sp = 0.0f;
    const int f0 = q * (NF / 4);
#pragma unroll 8
    for (int f = f0; f < f0 + NF / 4; ++f) {
        const float hv = hsh[f];
        mu = fmaf(hv, Wmu[f * NL + l], mu);
        sp = fmaf(hv, Wstd[f * NL + l], sp);
    }
    red_mu[q][l] = mu;
    red_sp[q][l] = sp;
    __syncthreads();

    if (q == 0) {
        mu = ((red_mu[0][l] + red_mu[1][l]) + (red_mu[2][l] + red_mu[3][l])) + bmu[l];
        sp = ((red_sp[0][l] + red_sp[1][l]) + (red_sp[2][l] + red_sp[3][l])) + bstd[l];
        const float stdv = softplus_f(sp);

        unsigned int nk0, nk1;
        tf2x32(0u, 0u, 0u, 1u, nk0, nk1);
        const int idx = b * NL + l;
        unsigned int o0, o1;
        tf2x32(nk0, nk1, 0u, (unsigned int)idx, o0, o1);
        const unsigned int bits = o0 ^ o1;
        const float f01 = __uint_as_float(0x3F800000u | (bits >> 9)) - 1.0f;
        float u = fmaf(f01, 2.0f, -0.99999994f);
        u = fmaxf(u, -0.99999994f);
        const float eps = 1.41421356237309515f * erfinv_xla(u);

        const float zs = mu + stdv * eps + actionbias[label[b] * NL + l];

        out[OFF_MU + idx]  = mu;
        out[OFF_STD + idx] = stdv;
        out[OFF_ZS + idx]  = zs;
        g_zs[idx] = zs;
    }
}

// ---------------------------------------------------------------------------
// K3: decoder GEMM via mma.sync bf16 split (hi/lo), persistent 296 blocks
// (2 CTAs/SM). Tile = 64 b (M) x 64 n (N) x K=128.
//   A = zs in smem [b][l] (272B rows), ldmatrix.x4 — built once.
//   W tile: register-prefetched LDG.128 -> cvt -> STS.64 into single smem
//   buffer [l][n] hi/lo (144B rows), ldmatrix.x2.trans.
//   3 passes: Ahi*Whi + Alo*Whi + Ahi*Wlo.
// ---------------------------------------------------------------------------
#define K3_GRID  296
#define K3_TILES (NTOT / 64)    // 8192
#define ROWB  272               // zs row stride
#define WROWB 144               // W row stride (64 bf16 + 16B pad)

#define ZS_H  0
#define ZS_L  (64 * ROWB)                   // 17408
#define W_H   (2 * 64 * ROWB)               // 34816
#define W_L   (W_H + 128 * WROWB)           // 53248
#define K3_SMEM (W_L + 128 * WROWB)         // 71680

__global__ __launch_bounds__(256, 2) void k3_decoder_mma(const float* __restrict__ Wd,
                                                         const float* __restrict__ bdec,
                                                         float* __restrict__ out_loc) {
    extern __shared__ char smem[];
    const uint32_t sb = smem_to_u32(smem);
    const int tid  = threadIdx.x;
    const int wid  = tid >> 5;
    const int lane = tid & 31;
    const int tl0  = tid >> 4;        // staging: base l row (0..15)
    const int tn8  = (tid & 15) * 8;  // staging: byte offset of 4-n group

    // --- prologue: zs hi/lo into smem [b][l] (built once) ---
    for (int i = tid; i < NB * NL; i += 256) {
        const int b = i >> 7;
        const int l = i & 127;
        const float v = g_zs[i];
        const __nv_bfloat16 hi = __float2bfloat16(v);
        const __nv_bfloat16 lo = __float2bfloat16(v - __bfloat162float(hi));
        *(__nv_bfloat16*)(smem + ZS_H + b * ROWB + l * 2) = hi;
        *(__nv_bfloat16*)(smem + ZS_L + b * ROWB + l * 2) = lo;
    }

    float4 wv[8];

    // load W tile into registers (8 x LDG.128 per thread)
#define K3_LOAD(tile_) do { \
        const float* _src = Wd + (long long)(tile_) * 64 + (tn8 >> 1); \
        _Pragma("unroll") \
        for (int p = 0; p < 8; ++p) \
            wv[p] = *(const float4*)(_src + (long long)(tl0 + p * 16) * NTOT); \
    } while (0)

    // convert registers -> hi/lo bf16 smem (STS.64)
#define K3_STORE() do { \
        _Pragma("unroll") \
        for (int p = 0; p < 8; ++p) { \
            const int l = tl0 + p * 16; \
            const float4 v = wv[p]; \
            uint2 h, g; \
            h.x = pack_bf16x2(v.x, v.y); \
            h.y = pack_bf16x2(v.z, v.w); \
            g.x = pack_bf16x2(v.x - __uint_as_float((h.x & 0xffffu) << 16), \
                              v.y - __uint_as_float(h.x & 0xffff0000u)); \
            g.y = pack_bf16x2(v.z - __uint_as_float((h.y & 0xffffu) << 16), \
                              v.w - __uint_as_float(h.y & 0xffff0000u)); \
            *(uint2*)(smem + W_H + l * WROWB + tn8) = h; \
            *(uint2*)(smem + W_L + l * WROWB + tn8) = g; \
        } \
    } while (0)

    int tile = blockIdx.x;
    K3_LOAD(tile);
    K3_STORE();
    __syncthreads();

    const uint32_t arow = (uint32_t)(lane & 15) * ROWB + (uint32_t)(lane >> 4) * 16;
    const uint32_t brow = (uint32_t)(lane & 15) * WROWB + (uint32_t)wid * 16;

    for (; tile < K3_TILES; tile += K3_GRID) {
        const int next = tile + K3_GRID;
        if (next < K3_TILES) K3_LOAD(next);   // in flight under compute

        float acc[4][4];
#pragma unroll
        for (int mt = 0; mt < 4; ++mt)
#pragma unroll
            for (int r = 0; r < 4; ++r) acc[mt][r] = 0.0f;

#pragma unroll
        for (int ks = 0; ks < 8; ++ks) {
            uint32_t bh[2], bl[2];
            const uint32_t ba = (uint32_t)(16 * ks) * WROWB + brow;
            ldsm_x2_trans(bh, sb + W_H + ba);
            ldsm_x2_trans(bl, sb + W_L + ba);
#pragma unroll
            for (int mt = 0; mt < 4; ++mt) {
                uint32_t ah[4], al[4];
                const uint32_t aa = (uint32_t)(16 * mt) * ROWB + arow + (uint32_t)(ks * 32);
                ldsm_x4(ah, sb + ZS_H + aa);
                ldsm_x4(al, sb + ZS_L + aa);
                mma_bf16(acc[mt], ah, bh);
                mma_bf16(acc[mt], al, bh);
                mma_bf16(acc[mt], ah, bl);
            }
        }

        // epilogue: float2 stores
        {
            const long long n = (long long)tile * 64 + wid * 8 + 2 * (lane & 3);
            const float2 bd = *(const float2*)(bdec + n);
#pragma unroll
            for (int mt = 0; mt < 4; ++mt) {
                const int b = mt * 16 + (lane >> 2);
                float2 v0, v1;
                v0.x = acc[mt][0] + bd.x;  v0.y = acc[mt][1] + bd.y;
                v1.x = acc[mt][2] + bd.x;  v1.y = acc[mt][3] + bd.y;
                *(float2*)(out_loc + (long long)b * NTOT + n)       = v0;
                *(float2*)(out_loc + (long long)(b + 8) * NTOT + n) = v1;
            }
        }

        __syncthreads();                       // everyone done reading W smem
        if (next < K3_TILES) K3_STORE();       // write next tile
        __syncthreads();                       // W smem ready
    }
}

// ---------------------------------------------------------------------------
// Launch
// ---------------------------------------------------------------------------
extern "C" void kernel_launch(void* const* d_in, const int* in_sizes, int n_in,
                              void* d_out, int out_size) {
    const float* x          = (const float*)d_in[0];
    const int*   label      = (const int*)d_in[1];
    const float* actionbias = (const float*)d_in[2];
    const float* W_mu       = (const float*)d_in[3];
    const float* b_mu       = (const float*)d_in[4];
    const float* W_std      = (const float*)d_in[5];
    const float* b_std      = (const float*)d_in[6];
    const float* W_dec      = (const float*)d_in[7];
    const float* b_dec      = (const float*)d_in[8];
    const float* log_scale  = (const float*)d_in[9];
    float* out = (float*)d_out;

    static int smem_set = 0;
    if (!smem_set) {
        cudaFuncSetAttribute(k3_decoder_mma, cudaFuncAttributeMaxDynamicSharedMemorySize,
                             K3_SMEM);
        smem_set = 1;
    }

    dim3 g1(NB, NSEG);
    k1_pool<<<g1, 256>>>(x);
    k2_encode<<<NB + 1, 512>>>(W_mu, b_mu, W_std, b_std, actionbias, label, log_scale, out);
    k3_decoder_mma<<<K3_GRID, 256, K3_SMEM>>>(W_dec, b_dec, out + OFF_LOC);
}

// round 10
// speedup vs baseline: 2.3548x; 1.0580x over previous
#include <cuda_runtime.h>
#include <cuda_bf16.h>
#include <cuda_fp16.h>
#include <cstdint>

// ---------------------------------------------------------------------------
// Problem constants
// ---------------------------------------------------------------------------
#define NB 64
#define NT 512
#define NF 1024
#define NL 128
#define NTOT (NT * NF)          // 524288 = T*F
#define NSEG 16                 // t-segments per batch in K1

// Output layout (flat concat in reference return order)
#define OFF_MU    0
#define OFF_STD   (NB * NL)                 // 8192
#define OFF_ZS    (2 * NB * NL)             // 16384
#define OFF_LOC   (3 * NB * NL)             // 24576
#define OFF_SCALE (3 * NB * NL + NB * NTOT) // 33579008

// ---------------------------------------------------------------------------
// Device scratch (no allocation allowed)
// ---------------------------------------------------------------------------
__device__ float g_hpart[NB * NSEG * NF];   // partial sums
__device__ float g_cntpart[NB * NSEG];      // partial mask counts
__device__ float g_zs[NB * NL];             // zs for decoder

// ---------------------------------------------------------------------------
// Small helpers
// ---------------------------------------------------------------------------
__device__ __forceinline__ float softplus_f(float v) {
    return fmaxf(v, 0.0f) + log1pf(expf(-fabsf(v)));
}

// Threefry-2x32, 20 rounds — exact JAX key schedule
__device__ __forceinline__ void tf2x32(unsigned int k0, unsigned int k1,
                                       unsigned int x0, unsigned int x1,
                                       unsigned int& o0, unsigned int& o1) {
    unsigned int ks2 = k0 ^ k1 ^ 0x1BD11BDAu;
    x0 += k0; x1 += k1;
#define TF_R(r) { x0 += x1; x1 = (x1 << (r)) | (x1 >> (32 - (r))); x1 ^= x0; }
    TF_R(13) TF_R(15) TF_R(26) TF_R(6)
    x0 += k1;  x1 += ks2 + 1u;
    TF_R(17) TF_R(29) TF_R(16) TF_R(24)
    x0 += ks2; x1 += k0 + 2u;
    TF_R(13) TF_R(15) TF_R(26) TF_R(6)
    x0 += k0;  x1 += k1 + 3u;
    TF_R(17) TF_R(29) TF_R(16) TF_R(24)
    x0 += k1;  x1 += ks2 + 4u;
    TF_R(13) TF_R(15) TF_R(26) TF_R(6)
    x0 += ks2; x1 += k0 + 5u;
#undef TF_R
    o0 = x0; o1 = x1;
}

// XLA f32 erf_inv (Giles polynomial)
__device__ __forceinline__ float erfinv_xla(float x) {
    float w = -log1pf(-x * x);
    float p;
    if (w < 5.0f) {
        w = w - 2.5f;
        p = 2.81022636e-08f;
        p = fmaf(p, w, 3.43273939e-07f);
        p = fmaf(p, w, -3.5233877e-06f);
        p = fmaf(p, w, -4.39150654e-06f);
        p = fmaf(p, w, 0.00021858087f);
        p = fmaf(p, w, -0.00125372503f);
        p = fmaf(p, w, -0.00417768164f);
        p = fmaf(p, w, 0.246640727f);
        p = fmaf(p, w, 1.50140941f);
    } else {
        w = sqrtf(w) - 3.0f;
        p = -0.000200214257f;
        p = fmaf(p, w, 0.000100950558f);
        p = fmaf(p, w, 0.00134934322f);
        p = fmaf(p, w, -0.00367342844f);
        p = fmaf(p, w, 0.00573950773f);
        p = fmaf(p, w, -0.0076224613f);
        p = fmaf(p, w, 0.00943887047f);
        p = fmaf(p, w, 1.00167406f);
        p = fmaf(p, w, 2.83297682f);
    }
    return p * x;
}

// ---------------------------------------------------------------------------
// mma.sync / ldmatrix helpers (portable sm_80+ PTX)
// ---------------------------------------------------------------------------
__device__ __forceinline__ uint32_t smem_to_u32(const void* smem_ptr) {
    uint32_t addr;
    asm("{ .reg .u64 tmp; cvta.to.shared.u64 tmp, %1; cvt.u32.u64 %0, tmp; }"
        : "=r"(addr) : "l"(smem_ptr));
    return addr;
}

__device__ __forceinline__ void ldsm_x4(uint32_t* r, uint32_t addr) {
    asm volatile("ldmatrix.sync.aligned.m8n8.x4.shared.b16 {%0,%1,%2,%3}, [%4];"
        : "=r"(r[0]), "=r"(r[1]), "=r"(r[2]), "=r"(r[3]) : "r"(addr));
}

__device__ __forceinline__ void ldsm_x2_trans(uint32_t* r, uint32_t addr) {
    asm volatile("ldmatrix.sync.aligned.m8n8.x2.trans.shared.b16 {%0,%1}, [%2];"
        : "=r"(r[0]), "=r"(r[1]) : "r"(addr));
}

__device__ __forceinline__ void mma_f16(float* d, const uint32_t* a, const uint32_t* b) {
    asm volatile(
        "mma.sync.aligned.m16n8k16.row.col.f32.f16.f16.f32 "
        "{%0,%1,%2,%3}, {%4,%5,%6,%7}, {%8,%9}, {%0,%1,%2,%3};"
        : "+f"(d[0]), "+f"(d[1]), "+f"(d[2]), "+f"(d[3])
        : "r"(a[0]), "r"(a[1]), "r"(a[2]), "r"(a[3]), "r"(b[0]), "r"(b[1]));
}

__device__ __forceinline__ uint32_t pack_h2(float x, float y) {
    __half2 h = __floats2half2_rn(x, y);
    return *(uint32_t*)&h;
}

// ---------------------------------------------------------------------------
// K1: column-sum over t (mask only affects the count).  grid (NB, NSEG).
// Masked rows are all-zero rows -> unconditional accumulation is identical.
// ---------------------------------------------------------------------------
__global__ __launch_bounds__(256, 4) void k1_pool(const float* __restrict__ x) {
    const int b = blockIdx.x;
    const int s = blockIdx.y;
    const int warp = threadIdx.x >> 5;
    const int lane = threadIdx.x & 31;

    __shared__ float hsh[NF];
    __shared__ int cnt_sh;
    for (int i = threadIdx.x; i < NF; i += 256) hsh[i] = 0.0f;
    if (threadIdx.x == 0) cnt_sh = 0;
    __syncthreads();

    float4 acc[8];
#pragma unroll
    for (int j = 0; j < 8; ++j) acc[j] = make_float4(0.f, 0.f, 0.f, 0.f);
    int cnt = 0;

    const float* xb = x + ((long long)b * NT + s * (NT / NSEG)) * NF;
    const int rows = NT / NSEG;  // 32
    for (int r = warp; r < rows; r += 8) {
        const float4* row4 = (const float4*)(xb + (long long)r * NF);
        float sum = 0.0f;
#pragma unroll
        for (int j = 0; j < 8; ++j) {
            const float4 v = row4[lane + 32 * j];
            acc[j].x += v.x; acc[j].y += v.y;
            acc[j].z += v.z; acc[j].w += v.w;
            sum += (v.x + v.y) + (v.z + v.w);
        }
#pragma unroll
        for (int o = 16; o > 0; o >>= 1) sum += __shfl_xor_sync(0xffffffffu, sum, o);
        if (sum != 0.0f) cnt++;
    }

#pragma unroll
    for (int j = 0; j < 8; ++j) {
        const int base = (lane + 32 * j) * 4;
        atomicAdd(&hsh[base + 0], acc[j].x);
        atomicAdd(&hsh[base + 1], acc[j].y);
        atomicAdd(&hsh[base + 2], acc[j].z);
        atomicAdd(&hsh[base + 3], acc[j].w);
    }
    if (lane == 0) atomicAdd(&cnt_sh, cnt);
    __syncthreads();

    const int part = b * NSEG + s;
    for (int i = threadIdx.x; i < NF; i += 256) g_hpart[part * NF + i] = hsh[i];
    if (threadIdx.x == 0) g_cntpart[part] = (float)cnt_sh;
}

// ---------------------------------------------------------------------------
// K2: encoder heads + threefry eps + zs.  grid NB+1, 512 threads.
// Extra block writes scale = softplus(log_scale).
// ---------------------------------------------------------------------------
__global__ __launch_bounds__(512) void k2_encode(
    const float* __restrict__ Wmu, const float* __restrict__ bmu,
    const float* __restrict__ Wstd, const float* __restrict__ bstd,
    const float* __restrict__ actionbias, const int* __restrict__ label,
    const float* __restrict__ log_scale,
    float* __restrict__ out) {
    if (blockIdx.x == NB) {
        for (int f = threadIdx.x; f < NF; f += 512)
            out[OFF_SCALE + f] = softplus_f(log_scale[f]);
        return;
    }
    const int b = blockIdx.x;
    const int l = threadIdx.x & 127;
    const int q = threadIdx.x >> 7;   // 0..3

    __shared__ float hsh[NF];
    __shared__ float red_mu[4][NL];
    __shared__ float red_sp[4][NL];
    __shared__ float inv_denom;

    for (int f = threadIdx.x; f < NF; f += 512) {
        float sum = 0.0f;
#pragma unroll
        for (int p = 0; p < NSEG; ++p) sum += g_hpart[(b * NSEG + p) * NF + f];
        hsh[f] = sum;
    }
    if (threadIdx.x == 0) {
        float c = 0.0f;
#pragma unroll
        for (int p = 0; p < NSEG; ++p) c += g_cntpart[b * NSEG + p];
        inv_denom = 1.0f / fmaxf(c, 1.0f);
    }
    __syncthreads();
    const float inv = inv_denom;
    for (int f = threadIdx.x; f < NF; f += 512) hsh[f] *= inv;
    __syncthreads();

    float mu = 0.0f;
    float sp = 0.0f;
    const int f0 = q * (NF / 4);
#pragma unroll 8
    for (int f = f0; f < f0 + NF / 4; ++f) {
        const float hv = hsh[f];
        mu = fmaf(hv, Wmu[f * NL + l], mu);
        sp = fmaf(hv, Wstd[f * NL + l], sp);
    }
    red_mu[q][l] = mu;
    red_sp[q][l] = sp;
    __syncthreads();

    if (q == 0) {
        mu = ((red_mu[0][l] + red_mu[1][l]) + (red_mu[2][l] + red_mu[3][l])) + bmu[l];
        sp = ((red_sp[0][l] + red_sp[1][l]) + (red_sp[2][l] + red_sp[3][l])) + bstd[l];
        const float stdv = softplus_f(sp);

        unsigned int nk0, nk1;
        tf2x32(0u, 0u, 0u, 1u, nk0, nk1);
        const int idx = b * NL + l;
        unsigned int o0, o1;
        tf2x32(nk0, nk1, 0u, (unsigned int)idx, o0, o1);
        const unsigned int bits = o0 ^ o1;
        const float f01 = __uint_as_float(0x3F800000u | (bits >> 9)) - 1.0f;
        float u = fmaf(f01, 2.0f, -0.99999994f);
        u = fmaxf(u, -0.99999994f);
        const float eps = 1.41421356237309515f * erfinv_xla(u);

        const float zs = mu + stdv * eps + actionbias[label[b] * NL + l];

        out[OFF_MU + idx]  = mu;
        out[OFF_STD + idx] = stdv;
        out[OFF_ZS + idx]  = zs;
        g_zs[idx] = zs;
    }
}

// ---------------------------------------------------------------------------
// K3: decoder GEMM via mma.sync fp16 2-pass (z split hi/lo, W single fp16).
//   computed = sum_l (zhi+zlo)[b,l] * fp16(W)[l,n]  — error = z*(W-fp16(W))
//   ~3e-4 norm relative, under the 1e-3 threshold.
// Persistent 296 blocks (2 CTAs/SM). Tile = 64 b x 64 n x K=128.
//   A = zs hi/lo fp16 in smem [b][l] (272B rows), ldmatrix.x4 — built once.
//   W tile: register-prefetched LDG.128 -> cvt fp16 -> STS.64 (144B rows),
//   ldmatrix.x2.trans.
// ---------------------------------------------------------------------------
#define K3_GRID  296
#define K3_TILES (NTOT / 64)    // 8192
#define ROWB  272               // zs row stride
#define WROWB 144               // W row stride (64 fp16 + 16B pad)

#define ZS_H  0
#define ZS_L  (64 * ROWB)                   // 17408
#define W_H   (2 * 64 * ROWB)               // 34816
#define K3_SMEM (W_H + 128 * WROWB)         // 53248

__global__ __launch_bounds__(256, 2) void k3_decoder_mma(const float* __restrict__ Wd,
                                                         const float* __restrict__ bdec,
                                                         float* __restrict__ out_loc) {
    extern __shared__ char smem[];
    const uint32_t sb = smem_to_u32(smem);
    const int tid  = threadIdx.x;
    const int wid  = tid >> 5;
    const int lane = tid & 31;
    const int tl0  = tid >> 4;        // staging: base l row (0..15)
    const int tn8  = (tid & 15) * 8;  // staging: byte offset in f32 gmem terms

    // --- prologue: zs hi/lo fp16 into smem [b][l] (built once) ---
    for (int i = tid; i < NB * NL; i += 256) {
        const int b = i >> 7;
        const int l = i & 127;
        const float v = g_zs[i];
        const __half hi = __float2half_rn(v);
        const __half lo = __float2half_rn(v - __half2float(hi));
        *(__half*)(smem + ZS_H + b * ROWB + l * 2) = hi;
        *(__half*)(smem + ZS_L + b * ROWB + l * 2) = lo;
    }

    float4 wv[8];

    // load W tile into registers (8 x LDG.128 per thread)
#define K3_LOAD(tile_) do { \
        const float* _src = Wd + (long long)(tile_) * 64 + (tn8 >> 1); \
        _Pragma("unroll") \
        for (int p = 0; p < 8; ++p) \
            wv[p] = *(const float4*)(_src + (long long)(tl0 + p * 16) * NTOT); \
    } while (0)

    // convert registers -> fp16 smem (STS.64), 4 n per thread-slot
#define K3_STORE() do { \
        _Pragma("unroll") \
        for (int p = 0; p < 8; ++p) { \
            const int l = tl0 + p * 16; \
            const float4 v = wv[p]; \
            uint2 h; \
            h.x = pack_h2(v.x, v.y); \
            h.y = pack_h2(v.z, v.w); \
            *(uint2*)(smem + W_H + l * WROWB + tn8) = h; \
        } \
    } while (0)

    int tile = blockIdx.x;
    K3_LOAD(tile);
    K3_STORE();
    __syncthreads();

    const uint32_t arow = (uint32_t)(lane & 15) * ROWB + (uint32_t)(lane >> 4) * 16;
    const uint32_t brow = (uint32_t)(lane & 15) * WROWB + (uint32_t)wid * 16;

    for (; tile < K3_TILES; tile += K3_GRID) {
        const int next = tile + K3_GRID;
        if (next < K3_TILES) K3_LOAD(next);   // in flight under compute

        float acc[4][4];
#pragma unroll
        for (int mt = 0; mt < 4; ++mt)
#pragma unroll
            for (int r = 0; r < 4; ++r) acc[mt][r] = 0.0f;

#pragma unroll
        for (int ks = 0; ks < 8; ++ks) {
            uint32_t bh[2];
            ldsm_x2_trans(bh, sb + W_H + (uint32_t)(16 * ks) * WROWB + brow);
#pragma unroll
            for (int mt = 0; mt < 4; ++mt) {
                uint32_t ah[4], al[4];
                const uint32_t aa = (uint32_t)(16 * mt) * ROWB + arow + (uint32_t)(ks * 32);
                ldsm_x4(ah, sb + ZS_H + aa);
                ldsm_x4(al, sb + ZS_L + aa);
                mma_f16(acc[mt], ah, bh);
                mma_f16(acc[mt], al, bh);
            }
        }

        // epilogue: float2 stores
        {
            const long long n = (long long)tile * 64 + wid * 8 + 2 * (lane & 3);
            const float2 bd = *(const float2*)(bdec + n);
#pragma unroll
            for (int mt = 0; mt < 4; ++mt) {
                const int b = mt * 16 + (lane >> 2);
                float2 v0, v1;
                v0.x = acc[mt][0] + bd.x;  v0.y = acc[mt][1] + bd.y;
                v1.x = acc[mt][2] + bd.x;  v1.y = acc[mt][3] + bd.y;
                *(float2*)(out_loc + (long long)b * NTOT + n)       = v0;
                *(float2*)(out_loc + (long long)(b + 8) * NTOT + n) = v1;
            }
        }

        __syncthreads();                       // everyone done reading W smem
        if (next < K3_TILES) K3_STORE();       // write next tile
        __syncthreads();                       // W smem ready
    }
}

// ---------------------------------------------------------------------------
// Launch
// ---------------------------------------------------------------------------
extern "C" void kernel_launch(void* const* d_in, const int* in_sizes, int n_in,
                              void* d_out, int out_size) {
    const float* x          = (const float*)d_in[0];
    const int*   label      = (const int*)d_in[1];
    const float* actionbias = (const float*)d_in[2];
    const float* W_mu       = (const float*)d_in[3];
    const float* b_mu       = (const float*)d_in[4];
    const float* W_std      = (const float*)d_in[5];
    const float* b_std      = (const float*)d_in[6];
    const float* W_dec      = (const float*)d_in[7];
    const float* b_dec      = (const float*)d_in[8];
    const float* log_scale  = (const float*)d_in[9];
    float* out = (float*)d_out;

    static int smem_set = 0;
    if (!smem_set) {
        cudaFuncSetAttribute(k3_decoder_mma, cudaFuncAttributeMaxDynamicSharedMemorySize,
                             K3_SMEM);
        smem_set = 1;
    }

    dim3 g1(NB, NSEG);
    k1_pool<<<g1, 256>>>(x);
    k2_encode<<<NB + 1, 512>>>(W_mu, b_mu, W_std, b_std, actionbias, label, log_scale, out);
    k3_decoder_mma<<<K3_GRID, 256, K3_SMEM>>>(W_dec, b_dec, out + OFF_LOC);
}

// round 11
// speedup vs baseline: 2.4885x; 1.0568x over previous
#include <cuda_runtime.h>
#include <cuda_bf16.h>
#include <cuda_fp16.h>
#include <cstdint>

// ---------------------------------------------------------------------------
// Problem constants
// ---------------------------------------------------------------------------
#define NB 64
#define NT 512
#define NF 1024
#define NL 128
#define NTOT (NT * NF)          // 524288 = T*F
#define NSEG 16                 // t-segments per batch in K1

// Output layout (flat concat in reference return order)
#define OFF_MU    0
#define OFF_STD   (NB * NL)                 // 8192
#define OFF_ZS    (2 * NB * NL)             // 16384
#define OFF_LOC   (3 * NB * NL)             // 24576
#define OFF_SCALE (3 * NB * NL + NB * NTOT) // 33579008

// ---------------------------------------------------------------------------
// Device scratch (no allocation allowed)
// ---------------------------------------------------------------------------
__device__ float g_hpart[NB * NSEG * NF];   // partial sums
__device__ float g_cntpart[NB * NSEG];      // partial mask counts
__device__ float g_zs[NB * NL];             // zs for decoder

// ---------------------------------------------------------------------------
// Small helpers
// ---------------------------------------------------------------------------
__device__ __forceinline__ float softplus_f(float v) {
    return fmaxf(v, 0.0f) + log1pf(expf(-fabsf(v)));
}

// Threefry-2x32, 20 rounds — exact JAX key schedule
__device__ __forceinline__ void tf2x32(unsigned int k0, unsigned int k1,
                                       unsigned int x0, unsigned int x1,
                                       unsigned int& o0, unsigned int& o1) {
    unsigned int ks2 = k0 ^ k1 ^ 0x1BD11BDAu;
    x0 += k0; x1 += k1;
#define TF_R(r) { x0 += x1; x1 = (x1 << (r)) | (x1 >> (32 - (r))); x1 ^= x0; }
    TF_R(13) TF_R(15) TF_R(26) TF_R(6)
    x0 += k1;  x1 += ks2 + 1u;
    TF_R(17) TF_R(29) TF_R(16) TF_R(24)
    x0 += ks2; x1 += k0 + 2u;
    TF_R(13) TF_R(15) TF_R(26) TF_R(6)
    x0 += k0;  x1 += k1 + 3u;
    TF_R(17) TF_R(29) TF_R(16) TF_R(24)
    x0 += k1;  x1 += ks2 + 4u;
    TF_R(13) TF_R(15) TF_R(26) TF_R(6)
    x0 += ks2; x1 += k0 + 5u;
#undef TF_R
    o0 = x0; o1 = x1;
}

// XLA f32 erf_inv (Giles polynomial)
__device__ __forceinline__ float erfinv_xla(float x) {
    float w = -log1pf(-x * x);
    float p;
    if (w < 5.0f) {
        w = w - 2.5f;
        p = 2.81022636e-08f;
        p = fmaf(p, w, 3.43273939e-07f);
        p = fmaf(p, w, -3.5233877e-06f);
        p = fmaf(p, w, -4.39150654e-06f);
        p = fmaf(p, w, 0.00021858087f);
        p = fmaf(p, w, -0.00125372503f);
        p = fmaf(p, w, -0.00417768164f);
        p = fmaf(p, w, 0.246640727f);
        p = fmaf(p, w, 1.50140941f);
    } else {
        w = sqrtf(w) - 3.0f;
        p = -0.000200214257f;
        p = fmaf(p, w, 0.000100950558f);
        p = fmaf(p, w, 0.00134934322f);
        p = fmaf(p, w, -0.00367342844f);
        p = fmaf(p, w, 0.00573950773f);
        p = fmaf(p, w, -0.0076224613f);
        p = fmaf(p, w, 0.00943887047f);
        p = fmaf(p, w, 1.00167406f);
        p = fmaf(p, w, 2.83297682f);
    }
    return p * x;
}

// ---------------------------------------------------------------------------
// mma.sync / ldmatrix helpers (portable sm_80+ PTX)
// ---------------------------------------------------------------------------
__device__ __forceinline__ uint32_t smem_to_u32(const void* smem_ptr) {
    uint32_t addr;
    asm("{ .reg .u64 tmp; cvta.to.shared.u64 tmp, %1; cvt.u32.u64 %0, tmp; }"
        : "=r"(addr) : "l"(smem_ptr));
    return addr;
}

__device__ __forceinline__ void ldsm_x4(uint32_t* r, uint32_t addr) {
    asm volatile("ldmatrix.sync.aligned.m8n8.x4.shared.b16 {%0,%1,%2,%3}, [%4];"
        : "=r"(r[0]), "=r"(r[1]), "=r"(r[2]), "=r"(r[3]) : "r"(addr));
}

__device__ __forceinline__ void ldsm_x2_trans(uint32_t* r, uint32_t addr) {
    asm volatile("ldmatrix.sync.aligned.m8n8.x2.trans.shared.b16 {%0,%1}, [%2];"
        : "=r"(r[0]), "=r"(r[1]) : "r"(addr));
}

__device__ __forceinline__ void mma_f16(float* d, const uint32_t* a, const uint32_t* b) {
    asm volatile(
        "mma.sync.aligned.m16n8k16.row.col.f32.f16.f16.f32 "
        "{%0,%1,%2,%3}, {%4,%5,%6,%7}, {%8,%9}, {%0,%1,%2,%3};"
        : "+f"(d[0]), "+f"(d[1]), "+f"(d[2]), "+f"(d[3])
        : "r"(a[0]), "r"(a[1]), "r"(a[2]), "r"(a[3]), "r"(b[0]), "r"(b[1]));
}

__device__ __forceinline__ uint32_t pack_h2(float x, float y) {
    __half2 h = __floats2half2_rn(x, y);
    return *(uint32_t*)&h;
}

// ---------------------------------------------------------------------------
// K1: column-sum over t (mask only affects the count).  grid (NB, NSEG).
// Two rows in flight per warp iteration (MLP=16).
// ---------------------------------------------------------------------------
__global__ __launch_bounds__(256, 3) void k1_pool(const float* __restrict__ x) {
    const int b = blockIdx.x;
    const int s = blockIdx.y;
    const int warp = threadIdx.x >> 5;
    const int lane = threadIdx.x & 31;

    __shared__ float hsh[NF];
    __shared__ int cnt_sh;
    for (int i = threadIdx.x; i < NF; i += 256) hsh[i] = 0.0f;
    if (threadIdx.x == 0) cnt_sh = 0;
    __syncthreads();

    float4 acc[8];
#pragma unroll
    for (int j = 0; j < 8; ++j) acc[j] = make_float4(0.f, 0.f, 0.f, 0.f);
    int cnt = 0;

    const float* xb = x + ((long long)b * NT + s * (NT / NSEG)) * NF;
    const int rows = NT / NSEG;  // 32
    for (int r = warp; r < rows; r += 16) {
        const float4* rowA = (const float4*)(xb + (long long)r * NF);
        const float4* rowB = (const float4*)(xb + (long long)(r + 8) * NF);
        float4 vA[8], vB[8];
#pragma unroll
        for (int j = 0; j < 8; ++j) vA[j] = rowA[lane + 32 * j];
#pragma unroll
        for (int j = 0; j < 8; ++j) vB[j] = rowB[lane + 32 * j];

        float sA = 0.0f, sB = 0.0f;
#pragma unroll
        for (int j = 0; j < 8; ++j) {
            acc[j].x += vA[j].x + vB[j].x;
            acc[j].y += vA[j].y + vB[j].y;
            acc[j].z += vA[j].z + vB[j].z;
            acc[j].w += vA[j].w + vB[j].w;
            sA += (vA[j].x + vA[j].y) + (vA[j].z + vA[j].w);
            sB += (vB[j].x + vB[j].y) + (vB[j].z + vB[j].w);
        }
#pragma unroll
        for (int o = 16; o > 0; o >>= 1) {
            sA += __shfl_xor_sync(0xffffffffu, sA, o);
            sB += __shfl_xor_sync(0xffffffffu, sB, o);
        }
        if (sA != 0.0f) cnt++;
        if (sB != 0.0f) cnt++;
    }

#pragma unroll
    for (int j = 0; j < 8; ++j) {
        const int base = (lane + 32 * j) * 4;
        atomicAdd(&hsh[base + 0], acc[j].x);
        atomicAdd(&hsh[base + 1], acc[j].y);
        atomicAdd(&hsh[base + 2], acc[j].z);
        atomicAdd(&hsh[base + 3], acc[j].w);
    }
    if (lane == 0) atomicAdd(&cnt_sh, cnt);
    __syncthreads();

    const int part = b * NSEG + s;
    for (int i = threadIdx.x; i < NF; i += 256) g_hpart[part * NF + i] = hsh[i];
    if (threadIdx.x == 0) g_cntpart[part] = (float)cnt_sh;
}

// ---------------------------------------------------------------------------
// K2: encoder heads + threefry eps + zs.  grid NB+1, 512 threads.
// Extra block writes scale = softplus(log_scale).
// ---------------------------------------------------------------------------
__global__ __launch_bounds__(512) void k2_encode(
    const float* __restrict__ Wmu, const float* __restrict__ bmu,
    const float* __restrict__ Wstd, const float* __restrict__ bstd,
    const float* __restrict__ actionbias, const int* __restrict__ label,
    const float* __restrict__ log_scale,
    float* __restrict__ out) {
    if (blockIdx.x == NB) {
        for (int f = threadIdx.x; f < NF; f += 512)
            out[OFF_SCALE + f] = softplus_f(log_scale[f]);
        return;
    }
    const int b = blockIdx.x;
    const int l = threadIdx.x & 127;
    const int q = threadIdx.x >> 7;   // 0..3

    __shared__ float hsh[NF];
    __shared__ float red_mu[4][NL];
    __shared__ float red_sp[4][NL];
    __shared__ float inv_denom;

    for (int f = threadIdx.x; f < NF; f += 512) {
        float sum = 0.0f;
#pragma unroll
        for (int p = 0; p < NSEG; ++p) sum += g_hpart[(b * NSEG + p) * NF + f];
        hsh[f] = sum;
    }
    if (threadIdx.x == 0) {
        float c = 0.0f;
#pragma unroll
        for (int p = 0; p < NSEG; ++p) c += g_cntpart[b * NSEG + p];
        inv_denom = 1.0f / fmaxf(c, 1.0f);
    }
    __syncthreads();
    const float inv = inv_denom;
    for (int f = threadIdx.x; f < NF; f += 512) hsh[f] *= inv;
    __syncthreads();

    float mu = 0.0f;
    float sp = 0.0f;
    const int f0 = q * (NF / 4);
#pragma unroll 8
    for (int f = f0; f < f0 + NF / 4; ++f) {
        const float hv = hsh[f];
        mu = fmaf(hv, Wmu[f * NL + l], mu);
        sp = fmaf(hv, Wstd[f * NL + l], sp);
    }
    red_mu[q][l] = mu;
    red_sp[q][l] = sp;
    __syncthreads();

    if (q == 0) {
        mu = ((red_mu[0][l] + red_mu[1][l]) + (red_mu[2][l] + red_mu[3][l])) + bmu[l];
        sp = ((red_sp[0][l] + red_sp[1][l]) + (red_sp[2][l] + red_sp[3][l])) + bstd[l];
        const float stdv = softplus_f(sp);

        unsigned int nk0, nk1;
        tf2x32(0u, 0u, 0u, 1u, nk0, nk1);
        const int idx = b * NL + l;
        unsigned int o0, o1;
        tf2x32(nk0, nk1, 0u, (unsigned int)idx, o0, o1);
        const unsigned int bits = o0 ^ o1;
        const float f01 = __uint_as_float(0x3F800000u | (bits >> 9)) - 1.0f;
        float u = fmaf(f01, 2.0f, -0.99999994f);
        u = fmaxf(u, -0.99999994f);
        const float eps = 1.41421356237309515f * erfinv_xla(u);

        const float zs = mu + stdv * eps + actionbias[label[b] * NL + l];

        out[OFF_MU + idx]  = mu;
        out[OFF_STD + idx] = stdv;
        out[OFF_ZS + idx]  = zs;
        g_zs[idx] = zs;
    }
}

// ---------------------------------------------------------------------------
// K3: decoder GEMM via mma.sync fp16 2-pass (z split hi/lo, W single fp16).
// Persistent 296 blocks (2 CTAs/SM). Tile = 64 b x 64 n x K=128.
// Warp grid 2(M) x 4(N): warp = 32 b x 16 n — cuts redundant A smem reads
// ~2x vs full-M warps (crossbar was the binder).
//   A = zs hi/lo fp16 in smem [b][l] (272B rows), ldmatrix.x4 — built once.
//   W tile: register-prefetched LDG.128 -> cvt fp16 -> STS.64 (144B rows),
//   ldmatrix.x2.trans.
// ---------------------------------------------------------------------------
#define K3_GRID  296
#define K3_TILES (NTOT / 64)    // 8192
#define ROWB  272               // zs row stride
#define WROWB 144               // W row stride (64 fp16 + 16B pad)

#define ZS_H  0
#define ZS_L  (64 * ROWB)                   // 17408
#define W_H   (2 * 64 * ROWB)               // 34816
#define K3_SMEM (W_H + 128 * WROWB)         // 53248

__global__ __launch_bounds__(256, 2) void k3_decoder_mma(const float* __restrict__ Wd,
                                                         const float* __restrict__ bdec,
                                                         float* __restrict__ out_loc) {
    extern __shared__ char smem[];
    const uint32_t sb = smem_to_u32(smem);
    const int tid  = threadIdx.x;
    const int wid  = tid >> 5;
    const int lane = tid & 31;
    const int wm   = wid & 1;         // M half (b 0-31 / 32-63)
    const int wn   = wid >> 1;        // n group of 16
    const int tl0  = tid >> 4;        // staging: base l row (0..15)
    const int tn8  = (tid & 15) * 8;  // staging: byte offset

    // --- prologue: zs hi/lo fp16 into smem [b][l] (built once) ---
    for (int i = tid; i < NB * NL; i += 256) {
        const int b = i >> 7;
        const int l = i & 127;
        const float v = g_zs[i];
        const __half hi = __float2half_rn(v);
        const __half lo = __float2half_rn(v - __half2float(hi));
        *(__half*)(smem + ZS_H + b * ROWB + l * 2) = hi;
        *(__half*)(smem + ZS_L + b * ROWB + l * 2) = lo;
    }

    float4 wv[8];

    // load W tile into registers (8 x LDG.128 per thread)
#define K3_LOAD(tile_) do { \
        const float* _src = Wd + (long long)(tile_) * 64 + (tn8 >> 1); \
        _Pragma("unroll") \
        for (int p = 0; p < 8; ++p) \
            wv[p] = *(const float4*)(_src + (long long)(tl0 + p * 16) * NTOT); \
    } while (0)

    // convert registers -> fp16 smem (STS.64), 4 n per thread-slot
#define K3_STORE() do { \
        _Pragma("unroll") \
        for (int p = 0; p < 8; ++p) { \
            const int l = tl0 + p * 16; \
            const float4 v = wv[p]; \
            uint2 h; \
            h.x = pack_h2(v.x, v.y); \
            h.y = pack_h2(v.z, v.w); \
            *(uint2*)(smem + W_H + l * WROWB + tn8) = h; \
        } \
    } while (0)

    int tile = blockIdx.x;
    K3_LOAD(tile);
    K3_STORE();
    __syncthreads();

    // A fragment base: rows wm*32 + (lane&15), col-halves by lane>>4
    const uint32_t arow = (uint32_t)(wm * 32 + (lane & 15)) * ROWB + (uint32_t)(lane >> 4) * 16;
    // B fragment base: rows (lane&15) of k-dim, n offset = wn*16 fp16
    const uint32_t brow = (uint32_t)(lane & 15) * WROWB + (uint32_t)wn * 32;

    for (; tile < K3_TILES; tile += K3_GRID) {
        const int next = tile + K3_GRID;
        if (next < K3_TILES) K3_LOAD(next);   // in flight under compute

        float acc[2][2][4];
#pragma unroll
        for (int mt = 0; mt < 2; ++mt)
#pragma unroll
            for (int nt = 0; nt < 2; ++nt)
#pragma unroll
                for (int r = 0; r < 4; ++r) acc[mt][nt][r] = 0.0f;

#pragma unroll
        for (int ks = 0; ks < 8; ++ks) {
            uint32_t bh[2][2];
            const uint32_t bb = (uint32_t)(16 * ks) * WROWB + brow;
            ldsm_x2_trans(bh[0], sb + W_H + bb);
            ldsm_x2_trans(bh[1], sb + W_H + bb + 16);
#pragma unroll
            for (int mt = 0; mt < 2; ++mt) {
                uint32_t ah[4], al[4];
                const uint32_t aa = (uint32_t)(16 * mt) * ROWB + arow + (uint32_t)(ks * 32);
                ldsm_x4(ah, sb + ZS_H + aa);
                ldsm_x4(al, sb + ZS_L + aa);
#pragma unroll
                for (int nt = 0; nt < 2; ++nt) {
                    mma_f16(acc[mt][nt], ah, bh[nt]);
                    mma_f16(acc[mt][nt], al, bh[nt]);
                }
            }
        }

        // epilogue: float2 stores
#pragma unroll
        for (int nt = 0; nt < 2; ++nt) {
            const long long n = (long long)tile * 64 + wn * 16 + nt * 8 + 2 * (lane & 3);
            const float2 bd = *(const float2*)(bdec + n);
#pragma unroll
            for (int mt = 0; mt < 2; ++mt) {
                const int b = wm * 32 + mt * 16 + (lane >> 2);
                float2 v0, v1;
                v0.x = acc[mt][nt][0] + bd.x;  v0.y = acc[mt][nt][1] + bd.y;
                v1.x = acc[mt][nt][2] + bd.x;  v1.y = acc[mt][nt][3] + bd.y;
                *(float2*)(out_loc + (long long)b * NTOT + n)       = v0;
                *(float2*)(out_loc + (long long)(b + 8) * NTOT + n) = v1;
            }
        }

        __syncthreads();                       // everyone done reading W smem
        if (next < K3_TILES) K3_STORE();       // write next tile
        __syncthreads();                       // W smem ready
    }
}

// ---------------------------------------------------------------------------
// Launch
// ---------------------------------------------------------------------------
extern "C" void kernel_launch(void* const* d_in, const int* in_sizes, int n_in,
                              void* d_out, int out_size) {
    const float* x          = (const float*)d_in[0];
    const int*   label      = (const int*)d_in[1];
    const float* actionbias = (const float*)d_in[2];
    const float* W_mu       = (const float*)d_in[3];
    const float* b_mu       = (const float*)d_in[4];
    const float* W_std      = (const float*)d_in[5];
    const float* b_std      = (const float*)d_in[6];
    const float* W_dec      = (const float*)d_in[7];
    const float* b_dec      = (const float*)d_in[8];
    const float* log_scale  = (const float*)d_in[9];
    float* out = (float*)d_out;

    static int smem_set = 0;
    if (!smem_set) {
        cudaFuncSetAttribute(k3_decoder_mma, cudaFuncAttributeMaxDynamicSharedMemorySize,
                             K3_SMEM);
        smem_set = 1;
    }

    dim3 g1(NB, NSEG);
    k1_pool<<<g1, 256>>>(x);
    k2_encode<<<NB + 1, 512>>>(W_mu, b_mu, W_std, b_std, actionbias, label, log_scale, out);
    k3_decoder_mma<<<K3_GRID, 256, K3_SMEM>>>(W_dec, b_dec, out + OFF_LOC);
}